// round 1
// baseline (speedup 1.0000x reference)
#include <cuda_runtime.h>

#define NB   2
#define NS   2048
#define ND   2048
#define NH   16
#define NDH  128
#define NTOK (NB * NS)

// Scratch (device globals: no allocation allowed in kernel_launch)
__device__ float g_Q [(size_t)NTOK * ND];    // roped Q, [tok][h*128+d]
__device__ float g_O [(size_t)NTOK * ND];    // attention output, [tok][h*128+d]
__device__ float g_KV[(size_t)NTOK * 2 * NDH]; // raw KV projection, [tok][256]
__device__ float g_Kr[(size_t)NTOK * NDH];   // roped K, [tok][128]

// ---------------------------------------------------------------------------
// Tiled SGEMM: C[M,N] = A[M,K] @ B     (TRANSB=0: B is [K,N];  TRANSB=1: B is [N,K])
// 128x128 tile, BK=8, 256 threads, 8x8 accumulators per thread.
// M,N,K all multiples of tile sizes here, no bounds checks needed.
// ---------------------------------------------------------------------------
template <int TRANSB>
__global__ void __launch_bounds__(256) sgemm_kernel(
    const float* __restrict__ A, const float* __restrict__ B,
    float* __restrict__ C, int M, int N, int K) {
  __shared__ float As[8][128];
  __shared__ float Bs[8][128];
  const int tid = threadIdx.x;
  const int bm = blockIdx.y * 128;
  const int bn = blockIdx.x * 128;
  const int ty = tid >> 4;        // 0..15
  const int tx = tid & 15;        // 0..15
  const int lrow = tid >> 1;      // 0..127
  const int lcol = (tid & 1) * 4; // 0 or 4

  float acc[8][8];
#pragma unroll
  for (int i = 0; i < 8; i++)
#pragma unroll
    for (int j = 0; j < 8; j++) acc[i][j] = 0.f;

  for (int k0 = 0; k0 < K; k0 += 8) {
    float4 av = *(const float4*)(A + (size_t)(bm + lrow) * K + k0 + lcol);
    As[lcol + 0][lrow] = av.x;
    As[lcol + 1][lrow] = av.y;
    As[lcol + 2][lrow] = av.z;
    As[lcol + 3][lrow] = av.w;
    if (TRANSB) {
      float4 bv = *(const float4*)(B + (size_t)(bn + lrow) * K + k0 + lcol);
      Bs[lcol + 0][lrow] = bv.x;
      Bs[lcol + 1][lrow] = bv.y;
      Bs[lcol + 2][lrow] = bv.z;
      Bs[lcol + 3][lrow] = bv.w;
    } else {
      int kk = tid >> 5;
      int nn = (tid & 31) * 4;
      *(float4*)&Bs[kk][nn] = *(const float4*)(B + (size_t)(k0 + kk) * N + bn + nn);
    }
    __syncthreads();
#pragma unroll
    for (int kk = 0; kk < 8; kk++) {
      float4 a0 = *(float4*)&As[kk][ty * 4];
      float4 a1 = *(float4*)&As[kk][64 + ty * 4];
      float4 b0 = *(float4*)&Bs[kk][tx * 4];
      float4 b1 = *(float4*)&Bs[kk][64 + tx * 4];
      float ar[8] = {a0.x, a0.y, a0.z, a0.w, a1.x, a1.y, a1.z, a1.w};
      float br[8] = {b0.x, b0.y, b0.z, b0.w, b1.x, b1.y, b1.z, b1.w};
#pragma unroll
      for (int i = 0; i < 8; i++)
#pragma unroll
        for (int j = 0; j < 8; j++) acc[i][j] = fmaf(ar[i], br[j], acc[i][j]);
    }
    __syncthreads();
  }

#pragma unroll
  for (int i = 0; i < 8; i++) {
    int row = bm + ty * 4 + (i & 3) + ((i >= 4) ? 64 : 0);
    *(float4*)(C + (size_t)row * N + bn + tx * 4) =
        make_float4(acc[i][0], acc[i][1], acc[i][2], acc[i][3]);
    *(float4*)(C + (size_t)row * N + bn + 64 + tx * 4) =
        make_float4(acc[i][4], acc[i][5], acc[i][6], acc[i][7]);
  }
}

// ---------------------------------------------------------------------------
// RoPE on Q, in-place. One block per token, 1024 threads: thread = (h, i<64).
// ---------------------------------------------------------------------------
__global__ void rope_q_kernel(float* __restrict__ Q, const int* __restrict__ past) {
  const int tok = blockIdx.x;
  const int s = tok % NS;
  const int pos = past[0] + s;
  const int t = threadIdx.x;
  const int h = t >> 6;
  const int i = t & 63;
  float fr = 1.0f / powf(10000.0f, (float)(2 * i) / 128.0f);
  float ang = (float)pos * fr;
  float sn, cs;
  sincosf(ang, &sn, &cs);
  float* q = Q + (size_t)tok * ND + h * NDH;
  float x1 = q[i];
  float x2 = q[i + 64];
  q[i]      = x1 * cs - x2 * sn;
  q[i + 64] = x2 * cs + x1 * sn;
}

// ---------------------------------------------------------------------------
// Split KV into K/V outputs and write roped K into scratch.
// One block per token, 128 threads.
// ---------------------------------------------------------------------------
__global__ void split_rope_k_kernel(const float* __restrict__ KV,
                                    float* __restrict__ Kout,
                                    float* __restrict__ Vout,
                                    float* __restrict__ Kr) {
  const int tok = blockIdx.x;
  const int s = tok % NS;
  const int t = threadIdx.x;  // 0..127
  const float* kv = KV + (size_t)tok * 256;
  Kout[(size_t)tok * NDH + t] = kv[t];
  Vout[(size_t)tok * NDH + t] = kv[128 + t];
  if (t < 64) {
    float fr = 1.0f / powf(10000.0f, (float)(2 * t) / 128.0f);
    float ang = (float)s * fr;
    float sn, cs;
    sincosf(ang, &sn, &cs);
    float x1 = kv[t];
    float x2 = kv[t + 64];
    Kr[(size_t)tok * NDH + t]      = x1 * cs - x2 * sn;
    Kr[(size_t)tok * NDH + t + 64] = x2 * cs + x1 * sn;
  }
}

// ---------------------------------------------------------------------------
// Flash attention (causal, MQA). Block = (qtile 64, head, batch). 256 threads.
// Online softmax. Thread (ty,tx): rows {ty+16i}, score cols {tx+16j},
// O cols {tx+16jj}.
// Shared: qs[64][128], ks[64][132], vs[64][132], ss[64][65].
// ---------------------------------------------------------------------------
#define ATTN_SMEM_FLOATS (64 * 128 + 64 * 132 + 64 * 132 + 64 * 65)

__global__ void __launch_bounds__(256) attn_kernel(
    const float* __restrict__ Q, const float* __restrict__ Kr,
    const float* __restrict__ KV, float* __restrict__ O,
    const int* __restrict__ past) {
  extern __shared__ float sm[];
  float* qs = sm;                  // stride 128
  float* ks = qs + 64 * 128;       // stride 132
  float* vs = ks + 64 * 132;       // stride 132
  float* ss = vs + 64 * 132;       // stride 65

  const int qt = blockIdx.x;
  const int h = blockIdx.y;
  const int b = blockIdx.z;
  const int tid = threadIdx.x;
  const int ty = tid >> 4;  // 0..15
  const int tx = tid & 15;  // 0..15
  const int q0 = qt * 64;
  const int pl = past[0];
  const float scale = 0.08838834764831845f;  // 1/sqrt(128)

  // Load Q tile (roped) into shared
  for (int i = tid; i < 64 * 32; i += 256) {
    int r = i >> 5, c = i & 31;
    *(float4*)(qs + r * 128 + c * 4) =
        *(const float4*)(Q + ((size_t)(b * NS + q0 + r)) * ND + h * NDH + c * 4);
  }

  float acc[4][8];
#pragma unroll
  for (int i = 0; i < 4; i++)
#pragma unroll
    for (int j = 0; j < 8; j++) acc[i][j] = 0.f;
  float mrow[4] = {-1e30f, -1e30f, -1e30f, -1e30f};
  float lrow[4] = {0.f, 0.f, 0.f, 0.f};

  for (int kt = 0; kt <= qt; kt++) {
    __syncthreads();  // protect ks/vs/ss from previous iteration's readers
    // Load K (roped) and V tiles
    for (int i = tid; i < 64 * 32; i += 256) {
      int r = i >> 5, c = i & 31;
      size_t tok = (size_t)(b * NS) + kt * 64 + r;
      *(float4*)(ks + r * 132 + c * 4) = *(const float4*)(Kr + tok * NDH + c * 4);
      *(float4*)(vs + r * 132 + c * 4) = *(const float4*)(KV + tok * 256 + 128 + c * 4);
    }
    __syncthreads();

    // Scores: sc[i][j] = q[ty+16i] . k[tx+16j]
    float sc[4][4];
#pragma unroll
    for (int i = 0; i < 4; i++)
#pragma unroll
      for (int j = 0; j < 4; j++) sc[i][j] = 0.f;

#pragma unroll 4
    for (int d4 = 0; d4 < 32; d4++) {
      float4 a[4], kq[4];
#pragma unroll
      for (int i = 0; i < 4; i++)
        a[i] = *(const float4*)(qs + (ty + 16 * i) * 128 + d4 * 4);
#pragma unroll
      for (int j = 0; j < 4; j++)
        kq[j] = *(const float4*)(ks + (tx + 16 * j) * 132 + d4 * 4);
#pragma unroll
      for (int i = 0; i < 4; i++)
#pragma unroll
        for (int j = 0; j < 4; j++) {
          sc[i][j] = fmaf(a[i].x, kq[j].x, sc[i][j]);
          sc[i][j] = fmaf(a[i].y, kq[j].y, sc[i][j]);
          sc[i][j] = fmaf(a[i].z, kq[j].z, sc[i][j]);
          sc[i][j] = fmaf(a[i].w, kq[j].w, sc[i][j]);
        }
    }

    // scale + causal mask (only the diagonal tile needs masking)
    if (kt == qt) {
#pragma unroll
      for (int i = 0; i < 4; i++) {
        int qi = q0 + ty + 16 * i + pl;
#pragma unroll
        for (int j = 0; j < 4; j++) {
          int kj = kt * 64 + tx + 16 * j;
          sc[i][j] = (kj <= qi) ? sc[i][j] * scale : -1e30f;
        }
      }
    } else {
#pragma unroll
      for (int i = 0; i < 4; i++)
#pragma unroll
        for (int j = 0; j < 4; j++) sc[i][j] *= scale;
    }

    // Row max across the 16 lanes sharing the same rows (tx dimension)
    float rmax[4];
#pragma unroll
    for (int i = 0; i < 4; i++) {
      float m = sc[i][0];
      m = fmaxf(m, sc[i][1]);
      m = fmaxf(m, sc[i][2]);
      m = fmaxf(m, sc[i][3]);
#pragma unroll
      for (int off = 8; off >= 1; off >>= 1)
        m = fmaxf(m, __shfl_xor_sync(0xffffffffu, m, off));
      rmax[i] = m;
    }

    float alpha[4], psum[4];
#pragma unroll
    for (int i = 0; i < 4; i++) {
      float mnew = fmaxf(mrow[i], rmax[i]);
      alpha[i] = __expf(mrow[i] - mnew);
      mrow[i] = mnew;
      float s0 = 0.f;
#pragma unroll
      for (int j = 0; j < 4; j++) {
        float p = __expf(sc[i][j] - mnew);
        ss[(ty + 16 * i) * 65 + tx + 16 * j] = p;
        s0 += p;
      }
#pragma unroll
      for (int off = 8; off >= 1; off >>= 1)
        s0 += __shfl_xor_sync(0xffffffffu, s0, off);
      psum[i] = s0;
    }
#pragma unroll
    for (int i = 0; i < 4; i++) {
      lrow[i] = lrow[i] * alpha[i] + psum[i];
#pragma unroll
      for (int j = 0; j < 8; j++) acc[i][j] *= alpha[i];
    }
    __syncthreads();

    // PV: acc[i][jj] += sum_j p[row_i][j] * v[j][tx+16jj]
#pragma unroll 4
    for (int j = 0; j < 64; j++) {
      float p0 = ss[(ty +  0) * 65 + j];
      float p1 = ss[(ty + 16) * 65 + j];
      float p2 = ss[(ty + 32) * 65 + j];
      float p3 = ss[(ty + 48) * 65 + j];
#pragma unroll
      for (int jj = 0; jj < 8; jj++) {
        float v = vs[j * 132 + tx + 16 * jj];
        acc[0][jj] = fmaf(p0, v, acc[0][jj]);
        acc[1][jj] = fmaf(p1, v, acc[1][jj]);
        acc[2][jj] = fmaf(p2, v, acc[2][jj]);
        acc[3][jj] = fmaf(p3, v, acc[3][jj]);
      }
    }
  }

  // Epilogue: normalize and write O[tok][h*128 + col]
#pragma unroll
  for (int i = 0; i < 4; i++) {
    float inv = 1.0f / lrow[i];
    size_t row = (size_t)(b * NS) + q0 + ty + 16 * i;
#pragma unroll
    for (int jj = 0; jj < 8; jj++)
      O[row * ND + h * NDH + tx + 16 * jj] = acc[i][jj] * inv;
  }
}

// ---------------------------------------------------------------------------
extern "C" void kernel_launch(void* const* d_in, const int* in_sizes, int n_in,
                              void* d_out, int out_size) {
  const float* x   = (const float*)d_in[0];
  const float* wq  = (const float*)d_in[1];
  const float* wkv = (const float*)d_in[2];
  const float* wo  = (const float*)d_in[3];
  const int*  past = (const int*)d_in[4];

  float* out  = (float*)d_out;
  float* Kout = out + (size_t)NTOK * ND;
  float* Vout = Kout + (size_t)NTOK * NDH;

  float *Qs, *Os, *KVs, *Krs;
  cudaGetSymbolAddress((void**)&Qs, g_Q);
  cudaGetSymbolAddress((void**)&Os, g_O);
  cudaGetSymbolAddress((void**)&KVs, g_KV);
  cudaGetSymbolAddress((void**)&Krs, g_Kr);

  const int attn_smem = ATTN_SMEM_FLOATS * (int)sizeof(float);
  cudaFuncSetAttribute(attn_kernel, cudaFuncAttributeMaxDynamicSharedMemorySize,
                       attn_smem);

  // Q = x @ wq.T
  sgemm_kernel<1><<<dim3(ND / 128, NTOK / 128), 256>>>(x, wq, Qs, NTOK, ND, ND);
  // KV = x @ wkv
  sgemm_kernel<0><<<dim3(2, NTOK / 128), 256>>>(x, wkv, KVs, NTOK, 256, ND);
  // RoPE Q in place
  rope_q_kernel<<<NTOK, 1024>>>(Qs, past);
  // Split K/V to outputs, rope K into scratch
  split_rope_k_kernel<<<NTOK, 128>>>(KVs, Kout, Vout, Krs);
  // Flash attention
  attn_kernel<<<dim3(NS / 64, NH, NB), 256, attn_smem>>>(Qs, Krs, KVs, Os, past);
  // out = o @ wo.T
  sgemm_kernel<1><<<dim3(ND / 128, NTOK / 128), 256>>>(Os, wo, out, NTOK, ND, ND);
}

// round 4
// speedup vs baseline: 1.6038x; 1.6038x over previous
#include <cuda_runtime.h>
#include <cstdint>

#define NB   2
#define NS   2048
#define ND   2048
#define NH   16
#define NDH  128
#define NTOK (NB * NS)

// Scratch (device globals: no allocation allowed in kernel_launch)
__device__ float g_Q [(size_t)NTOK * ND];      // roped Q, [tok][h*128+d]
__device__ float g_O [(size_t)NTOK * ND];      // attention output, [tok][h*128+d]
__device__ float g_KV[(size_t)NTOK * 2 * NDH]; // raw KV projection, [tok][256]
__device__ float g_Kr[(size_t)NTOK * NDH];     // roped K, [tok][128]

// ===========================================================================
// PTX helpers (portable sm_80+ subset: cp.async + mma.sync tf32)
// ===========================================================================
__device__ __forceinline__ uint32_t smem_u32(const void* p) {
  uint32_t a;
  asm("{ .reg .u64 t; cvta.to.shared.u64 t, %1; cvt.u32.u64 %0, t; }"
      : "=r"(a) : "l"(p));
  return a;
}

__device__ __forceinline__ void cp_async16(uint32_t dst, const void* src) {
  asm volatile("cp.async.cg.shared.global [%0], [%1], 16;" ::"r"(dst), "l"(src));
}
#define CP_ASYNC_COMMIT() asm volatile("cp.async.commit_group;" ::: "memory")
template <int N>
__device__ __forceinline__ void cp_async_wait() {
  asm volatile("cp.async.wait_group %0;" ::"n"(N) : "memory");
}

__device__ __forceinline__ uint32_t f2tf32(float x) {
  uint32_t r;
  asm("cvt.rna.tf32.f32 %0, %1;" : "=r"(r) : "f"(x));
  return r;
}

__device__ __forceinline__ void mma_tf32(float* c, const uint32_t* a,
                                         const uint32_t* b) {
  asm volatile(
      "mma.sync.aligned.m16n8k8.row.col.f32.tf32.tf32.f32 "
      "{%0,%1,%2,%3}, {%4,%5,%6,%7}, {%8,%9}, {%0,%1,%2,%3};"
      : "+f"(c[0]), "+f"(c[1]), "+f"(c[2]), "+f"(c[3])
      : "r"(a[0]), "r"(a[1]), "r"(a[2]), "r"(a[3]), "r"(b[0]), "r"(b[1]));
}

// ===========================================================================
// tf32 mma.sync GEMM: C[M,N] = A[M,K] @ B[N,K]^T  (both row-major / K-major)
// Tile 128x128x32, 256 threads (8 warps, 2x4), warp tile 64x32.
// 3-stage cp.async pipeline. Smem rows padded to 36 floats (conflict-free).
// ===========================================================================
#define TBM 128
#define TBN 128
#define TBK 32
#define TSTRIDE 36                          // floats per smem row
#define TILE_FLOATS (TBM * TSTRIDE)         // one operand tile
#define STAGE_FLOATS (2 * TILE_FLOATS)      // A + B per stage
#define TSTAGES 3
#define MMA_SMEM (TSTAGES * STAGE_FLOATS * 4)  // bytes = 110592

__global__ void __launch_bounds__(256, 1)
tf32_mma_gemm(const float* __restrict__ A, const float* __restrict__ B,
              float* __restrict__ C, int M, int N, int K) {
  extern __shared__ float sm[];
  const int tid = threadIdx.x;
  const int wid = tid >> 5;
  const int lane = tid & 31;
  const int gid = lane >> 2;  // groupID 0..7
  const int tg = lane & 3;    // threadID_in_group 0..3
  const int wm = wid & 1;     // warp m index (0..1) -> 64 rows
  const int wn = wid >> 1;    // warp n index (0..3) -> 32 cols
  const int bm = blockIdx.y * TBM;
  const int bn = blockIdx.x * TBN;
  const int nchunks = K / TBK;

  const float* gA = A + (size_t)bm * K;
  const float* gB = B + (size_t)bn * K;
  const uint32_t sbase = smem_u32(sm);

  auto load_chunk = [&](int c) {
    const int s = c % TSTAGES;
    const uint32_t sa = sbase + s * STAGE_FLOATS * 4;
    const uint32_t sbb = sa + TILE_FLOATS * 4;
    const int k0 = c * TBK;
#pragma unroll
    for (int i = 0; i < 4; i++) {
      int idx = tid + i * 256;
      int r = idx >> 3, c4 = idx & 7;
      cp_async16(sa + (r * TSTRIDE + c4 * 4) * 4, gA + (size_t)r * K + k0 + c4 * 4);
    }
#pragma unroll
    for (int i = 0; i < 4; i++) {
      int idx = tid + i * 256;
      int r = idx >> 3, c4 = idx & 7;
      cp_async16(sbb + (r * TSTRIDE + c4 * 4) * 4, gB + (size_t)r * K + k0 + c4 * 4);
    }
    CP_ASYNC_COMMIT();
  };

  float acc[4][4][4];
#pragma unroll
  for (int mf = 0; mf < 4; mf++)
#pragma unroll
    for (int nf = 0; nf < 4; nf++)
#pragma unroll
      for (int r = 0; r < 4; r++) acc[mf][nf][r] = 0.f;

  load_chunk(0);
  load_chunk(1);

  for (int i = 0; i < nchunks; i++) {
    if (i < nchunks - 1)
      cp_async_wait<1>();
    else
      cp_async_wait<0>();
    __syncthreads();

    if (i + 2 < nchunks) load_chunk(i + 2);

    const float* As = sm + (i % TSTAGES) * STAGE_FLOATS;
    const float* Bs = As + TILE_FLOATS;

#pragma unroll
    for (int k8 = 0; k8 < 4; k8++) {
      uint32_t a[4][4], b[4][2];
#pragma unroll
      for (int mf = 0; mf < 4; mf++) {
        const float* ap = As + (wm * 64 + mf * 16 + gid) * TSTRIDE + k8 * 8 + tg;
        a[mf][0] = f2tf32(ap[0]);
        a[mf][1] = f2tf32(ap[8 * TSTRIDE]);
        a[mf][2] = f2tf32(ap[4]);
        a[mf][3] = f2tf32(ap[8 * TSTRIDE + 4]);
      }
#pragma unroll
      for (int nf = 0; nf < 4; nf++) {
        const float* bp = Bs + (wn * 32 + nf * 8 + gid) * TSTRIDE + k8 * 8 + tg;
        b[nf][0] = f2tf32(bp[0]);
        b[nf][1] = f2tf32(bp[4]);
      }
#pragma unroll
      for (int mf = 0; mf < 4; mf++)
#pragma unroll
        for (int nf = 0; nf < 4; nf++) mma_tf32(acc[mf][nf], a[mf], b[nf]);
    }
    __syncthreads();
  }

  // Epilogue: c0,c1 contiguous; c2,c3 contiguous (row +8)
#pragma unroll
  for (int mf = 0; mf < 4; mf++) {
    int row0 = bm + wm * 64 + mf * 16 + gid;
#pragma unroll
    for (int nf = 0; nf < 4; nf++) {
      int col = bn + wn * 32 + nf * 8 + 2 * tg;
      *(float2*)(C + (size_t)row0 * N + col) =
          make_float2(acc[mf][nf][0], acc[mf][nf][1]);
      *(float2*)(C + (size_t)(row0 + 8) * N + col) =
          make_float2(acc[mf][nf][2], acc[mf][nf][3]);
    }
  }
}

// ===========================================================================
// fp32 SGEMM (kept for KV projection: N=256, fp32-exact for K/V outputs)
// ===========================================================================
__global__ void __launch_bounds__(256) sgemm_nt_kernel(
    const float* __restrict__ A, const float* __restrict__ B,
    float* __restrict__ C, int M, int N, int K) {
  __shared__ float As[8][128];
  __shared__ float Bs[8][128];
  const int tid = threadIdx.x;
  const int bm = blockIdx.y * 128;
  const int bn = blockIdx.x * 128;
  const int ty = tid >> 4;
  const int tx = tid & 15;
  const int lrow = tid >> 1;
  const int lcol = (tid & 1) * 4;

  float acc[8][8];
#pragma unroll
  for (int i = 0; i < 8; i++)
#pragma unroll
    for (int j = 0; j < 8; j++) acc[i][j] = 0.f;

  for (int k0 = 0; k0 < K; k0 += 8) {
    float4 av = *(const float4*)(A + (size_t)(bm + lrow) * K + k0 + lcol);
    As[lcol + 0][lrow] = av.x;
    As[lcol + 1][lrow] = av.y;
    As[lcol + 2][lrow] = av.z;
    As[lcol + 3][lrow] = av.w;
    {
      int kk = tid >> 5;
      int nn = (tid & 31) * 4;
      *(float4*)&Bs[kk][nn] = *(const float4*)(B + (size_t)(k0 + kk) * N + bn + nn);
    }
    __syncthreads();
#pragma unroll
    for (int kk = 0; kk < 8; kk++) {
      float4 a0 = *(float4*)&As[kk][ty * 4];
      float4 a1 = *(float4*)&As[kk][64 + ty * 4];
      float4 b0 = *(float4*)&Bs[kk][tx * 4];
      float4 b1 = *(float4*)&Bs[kk][64 + tx * 4];
      float ar[8] = {a0.x, a0.y, a0.z, a0.w, a1.x, a1.y, a1.z, a1.w};
      float br[8] = {b0.x, b0.y, b0.z, b0.w, b1.x, b1.y, b1.z, b1.w};
#pragma unroll
      for (int i = 0; i < 8; i++)
#pragma unroll
        for (int j = 0; j < 8; j++) acc[i][j] = fmaf(ar[i], br[j], acc[i][j]);
    }
    __syncthreads();
  }

#pragma unroll
  for (int i = 0; i < 8; i++) {
    int row = bm + ty * 4 + (i & 3) + ((i >= 4) ? 64 : 0);
    *(float4*)(C + (size_t)row * N + bn + tx * 4) =
        make_float4(acc[i][0], acc[i][1], acc[i][2], acc[i][3]);
    *(float4*)(C + (size_t)row * N + bn + 64 + tx * 4) =
        make_float4(acc[i][4], acc[i][5], acc[i][6], acc[i][7]);
  }
}

// ---------------------------------------------------------------------------
// RoPE on Q, in-place.
// ---------------------------------------------------------------------------
__global__ void rope_q_kernel(float* __restrict__ Q, const int* __restrict__ past) {
  const int tok = blockIdx.x;
  const int s = tok % NS;
  const int pos = past[0] + s;
  const int t = threadIdx.x;
  const int h = t >> 6;
  const int i = t & 63;
  float fr = 1.0f / powf(10000.0f, (float)(2 * i) / 128.0f);
  float ang = (float)pos * fr;
  float sn, cs;
  sincosf(ang, &sn, &cs);
  float* q = Q + (size_t)tok * ND + h * NDH;
  float x1 = q[i];
  float x2 = q[i + 64];
  q[i]      = x1 * cs - x2 * sn;
  q[i + 64] = x2 * cs + x1 * sn;
}

// ---------------------------------------------------------------------------
// Split KV into K/V outputs and write roped K into scratch.
// ---------------------------------------------------------------------------
__global__ void split_rope_k_kernel(const float* __restrict__ KV,
                                    float* __restrict__ Kout,
                                    float* __restrict__ Vout,
                                    float* __restrict__ Kr) {
  const int tok = blockIdx.x;
  const int s = tok % NS;
  const int t = threadIdx.x;
  const float* kv = KV + (size_t)tok * 256;
  Kout[(size_t)tok * NDH + t] = kv[t];
  Vout[(size_t)tok * NDH + t] = kv[128 + t];
  if (t < 64) {
    float fr = 1.0f / powf(10000.0f, (float)(2 * t) / 128.0f);
    float ang = (float)s * fr;
    float sn, cs;
    sincosf(ang, &sn, &cs);
    float x1 = kv[t];
    float x2 = kv[t + 64];
    Kr[(size_t)tok * NDH + t]      = x1 * cs - x2 * sn;
    Kr[(size_t)tok * NDH + t + 64] = x2 * cs + x1 * sn;
  }
}

// ---------------------------------------------------------------------------
// Flash attention (causal, MQA), fp32.
// ---------------------------------------------------------------------------
#define ATTN_SMEM_FLOATS (64 * 128 + 64 * 132 + 64 * 132 + 64 * 65)

__global__ void __launch_bounds__(256) attn_kernel(
    const float* __restrict__ Q, const float* __restrict__ Kr,
    const float* __restrict__ KV, float* __restrict__ O,
    const int* __restrict__ past) {
  extern __shared__ float sm[];
  float* qs = sm;
  float* ks = qs + 64 * 128;
  float* vs = ks + 64 * 132;
  float* ss = vs + 64 * 132;

  const int qt = blockIdx.x;
  const int h = blockIdx.y;
  const int b = blockIdx.z;
  const int tid = threadIdx.x;
  const int ty = tid >> 4;
  const int tx = tid & 15;
  const int q0 = qt * 64;
  const int pl = past[0];
  const float scale = 0.08838834764831845f;

  for (int i = tid; i < 64 * 32; i += 256) {
    int r = i >> 5, c = i & 31;
    *(float4*)(qs + r * 128 + c * 4) =
        *(const float4*)(Q + ((size_t)(b * NS + q0 + r)) * ND + h * NDH + c * 4);
  }

  float acc[4][8];
#pragma unroll
  for (int i = 0; i < 4; i++)
#pragma unroll
    for (int j = 0; j < 8; j++) acc[i][j] = 0.f;
  float mrow[4] = {-1e30f, -1e30f, -1e30f, -1e30f};
  float lrow[4] = {0.f, 0.f, 0.f, 0.f};

  for (int kt = 0; kt <= qt; kt++) {
    __syncthreads();
    for (int i = tid; i < 64 * 32; i += 256) {
      int r = i >> 5, c = i & 31;
      size_t tok = (size_t)(b * NS) + kt * 64 + r;
      *(float4*)(ks + r * 132 + c * 4) = *(const float4*)(Kr + tok * NDH + c * 4);
      *(float4*)(vs + r * 132 + c * 4) = *(const float4*)(KV + tok * 256 + 128 + c * 4);
    }
    __syncthreads();

    float sc[4][4];
#pragma unroll
    for (int i = 0; i < 4; i++)
#pragma unroll
      for (int j = 0; j < 4; j++) sc[i][j] = 0.f;

#pragma unroll 4
    for (int d4 = 0; d4 < 32; d4++) {
      float4 a[4], kq[4];
#pragma unroll
      for (int i = 0; i < 4; i++)
        a[i] = *(const float4*)(qs + (ty + 16 * i) * 128 + d4 * 4);
#pragma unroll
      for (int j = 0; j < 4; j++)
        kq[j] = *(const float4*)(ks + (tx + 16 * j) * 132 + d4 * 4);
#pragma unroll
      for (int i = 0; i < 4; i++)
#pragma unroll
        for (int j = 0; j < 4; j++) {
          sc[i][j] = fmaf(a[i].x, kq[j].x, sc[i][j]);
          sc[i][j] = fmaf(a[i].y, kq[j].y, sc[i][j]);
          sc[i][j] = fmaf(a[i].z, kq[j].z, sc[i][j]);
          sc[i][j] = fmaf(a[i].w, kq[j].w, sc[i][j]);
        }
    }

    if (kt == qt) {
#pragma unroll
      for (int i = 0; i < 4; i++) {
        int qi = q0 + ty + 16 * i + pl;
#pragma unroll
        for (int j = 0; j < 4; j++) {
          int kj = kt * 64 + tx + 16 * j;
          sc[i][j] = (kj <= qi) ? sc[i][j] * scale : -1e30f;
        }
      }
    } else {
#pragma unroll
      for (int i = 0; i < 4; i++)
#pragma unroll
        for (int j = 0; j < 4; j++) sc[i][j] *= scale;
    }

    float rmax[4];
#pragma unroll
    for (int i = 0; i < 4; i++) {
      float m = sc[i][0];
      m = fmaxf(m, sc[i][1]);
      m = fmaxf(m, sc[i][2]);
      m = fmaxf(m, sc[i][3]);
#pragma unroll
      for (int off = 8; off >= 1; off >>= 1)
        m = fmaxf(m, __shfl_xor_sync(0xffffffffu, m, off));
      rmax[i] = m;
    }

    float alpha[4], psum[4];
#pragma unroll
    for (int i = 0; i < 4; i++) {
      float mnew = fmaxf(mrow[i], rmax[i]);
      alpha[i] = __expf(mrow[i] - mnew);
      mrow[i] = mnew;
      float s0 = 0.f;
#pragma unroll
      for (int j = 0; j < 4; j++) {
        float p = __expf(sc[i][j] - mnew);
        ss[(ty + 16 * i) * 65 + tx + 16 * j] = p;
        s0 += p;
      }
#pragma unroll
      for (int off = 8; off >= 1; off >>= 1)
        s0 += __shfl_xor_sync(0xffffffffu, s0, off);
      psum[i] = s0;
    }
#pragma unroll
    for (int i = 0; i < 4; i++) {
      lrow[i] = lrow[i] * alpha[i] + psum[i];
#pragma unroll
      for (int j = 0; j < 8; j++) acc[i][j] *= alpha[i];
    }
    __syncthreads();

#pragma unroll 4
    for (int j = 0; j < 64; j++) {
      float p0 = ss[(ty +  0) * 65 + j];
      float p1 = ss[(ty + 16) * 65 + j];
      float p2 = ss[(ty + 32) * 65 + j];
      float p3 = ss[(ty + 48) * 65 + j];
#pragma unroll
      for (int jj = 0; jj < 8; jj++) {
        float v = vs[j * 132 + tx + 16 * jj];
        acc[0][jj] = fmaf(p0, v, acc[0][jj]);
        acc[1][jj] = fmaf(p1, v, acc[1][jj]);
        acc[2][jj] = fmaf(p2, v, acc[2][jj]);
        acc[3][jj] = fmaf(p3, v, acc[3][jj]);
      }
    }
  }

#pragma unroll
  for (int i = 0; i < 4; i++) {
    float inv = 1.0f / lrow[i];
    size_t row = (size_t)(b * NS) + q0 + ty + 16 * i;
#pragma unroll
    for (int jj = 0; jj < 8; jj++)
      O[row * ND + h * NDH + tx + 16 * jj] = acc[i][jj] * inv;
  }
}

// ---------------------------------------------------------------------------
extern "C" void kernel_launch(void* const* d_in, const int* in_sizes, int n_in,
                              void* d_out, int out_size) {
  const float* x   = (const float*)d_in[0];
  const float* wq  = (const float*)d_in[1];
  const float* wkv = (const float*)d_in[2];
  const float* wo  = (const float*)d_in[3];
  const int*  past = (const int*)d_in[4];

  float* out  = (float*)d_out;
  float* Kout = out + (size_t)NTOK * ND;
  float* Vout = Kout + (size_t)NTOK * NDH;

  float *Qs, *Os, *KVs, *Krs;
  cudaGetSymbolAddress((void**)&Qs, g_Q);
  cudaGetSymbolAddress((void**)&Os, g_O);
  cudaGetSymbolAddress((void**)&KVs, g_KV);
  cudaGetSymbolAddress((void**)&Krs, g_Kr);

  const int attn_smem = ATTN_SMEM_FLOATS * (int)sizeof(float);
  cudaFuncSetAttribute(attn_kernel, cudaFuncAttributeMaxDynamicSharedMemorySize,
                       attn_smem);
  cudaFuncSetAttribute(tf32_mma_gemm,
                       cudaFuncAttributeMaxDynamicSharedMemorySize, MMA_SMEM);

  // Q = x @ wq.T  (tf32 mma.sync)
  tf32_mma_gemm<<<dim3(ND / TBN, NTOK / TBM), 256, MMA_SMEM>>>(
      x, wq, Qs, NTOK, ND, ND);
  // KV = x @ wkv  (fp32 exact — K,V are outputs)
  sgemm_nt_kernel<<<dim3(2, NTOK / 128), 256>>>(x, wkv, KVs, NTOK, 256, ND);
  // RoPE Q in place
  rope_q_kernel<<<NTOK, 1024>>>(Qs, past);
  // Split K/V to outputs, rope K into scratch
  split_rope_k_kernel<<<NTOK, 128>>>(KVs, Kout, Vout, Krs);
  // Flash attention (fp32)
  attn_kernel<<<dim3(NS / 64, NH, NB), 256, attn_smem>>>(Qs, Krs, KVs, Os, past);
  // out = O @ wo.T  (tf32 mma.sync)
  tf32_mma_gemm<<<dim3(ND / TBN, NTOK / TBM), 256, MMA_SMEM>>>(
      Os, wo, out, NTOK, ND, ND);
}

// round 5
// speedup vs baseline: 2.4053x; 1.4997x over previous
#include <cuda_runtime.h>
#include <cstdint>

#define NB   2
#define NS   2048
#define ND   2048
#define NH   16
#define NDH  128
#define NTOK (NB * NS)

// Scratch (device globals: no allocation allowed in kernel_launch)
__device__ float g_Q [(size_t)NTOK * ND];      // roped Q (tf32-rounded), [tok][h*128+d]
__device__ float g_O [(size_t)NTOK * ND];      // attention output, [tok][h*128+d]
__device__ float g_KV[(size_t)NTOK * 2 * NDH]; // raw KV projection (exact), [tok][256]
__device__ float g_Kr[(size_t)NTOK * NDH];     // roped K (tf32-rounded), [tok][128]

// ===========================================================================
// PTX helpers (portable sm_80+ subset: cp.async + mma.sync tf32)
// ===========================================================================
__device__ __forceinline__ uint32_t smem_u32(const void* p) {
  uint32_t a;
  asm("{ .reg .u64 t; cvta.to.shared.u64 t, %1; cvt.u32.u64 %0, t; }"
      : "=r"(a) : "l"(p));
  return a;
}

__device__ __forceinline__ void cp_async16(uint32_t dst, const void* src) {
  asm volatile("cp.async.cg.shared.global [%0], [%1], 16;" ::"r"(dst), "l"(src));
}
#define CP_ASYNC_COMMIT() asm volatile("cp.async.commit_group;" ::: "memory")
template <int N>
__device__ __forceinline__ void cp_async_wait() {
  asm volatile("cp.async.wait_group %0;" ::"n"(N) : "memory");
}

__device__ __forceinline__ uint32_t f2tf32(float x) {
  uint32_t r;
  asm("cvt.rna.tf32.f32 %0, %1;" : "=r"(r) : "f"(x));
  return r;
}
__device__ __forceinline__ float f2tf32f(float x) {
  return __uint_as_float(f2tf32(x));
}

__device__ __forceinline__ void mma_tf32(float* c, const uint32_t* a,
                                         const uint32_t* b) {
  asm volatile(
      "mma.sync.aligned.m16n8k8.row.col.f32.tf32.tf32.f32 "
      "{%0,%1,%2,%3}, {%4,%5,%6,%7}, {%8,%9}, {%0,%1,%2,%3};"
      : "+f"(c[0]), "+f"(c[1]), "+f"(c[2]), "+f"(c[3])
      : "r"(a[0]), "r"(a[1]), "r"(a[2]), "r"(a[3]), "r"(b[0]), "r"(b[1]));
}

// ===========================================================================
// tf32 mma.sync GEMM: C[M,N] = A[M,K] @ B[N,K]^T  (both row-major / K-major)
// Tile 128x128x32, 256 threads (8 warps, 2x4), warp tile 64x32.
// ===========================================================================
#define TBM 128
#define TBN 128
#define TBK 32
#define TSTRIDE 36
#define TILE_FLOATS (TBM * TSTRIDE)
#define STAGE_FLOATS (2 * TILE_FLOATS)
#define TSTAGES 3
#define MMA_SMEM (TSTAGES * STAGE_FLOATS * 4)

__global__ void __launch_bounds__(256, 1)
tf32_mma_gemm(const float* __restrict__ A, const float* __restrict__ B,
              float* __restrict__ C, int M, int N, int K) {
  extern __shared__ float sm[];
  const int tid = threadIdx.x;
  const int wid = tid >> 5;
  const int lane = tid & 31;
  const int gid = lane >> 2;
  const int tg = lane & 3;
  const int wm = wid & 1;
  const int wn = wid >> 1;
  const int bm = blockIdx.y * TBM;
  const int bn = blockIdx.x * TBN;
  const int nchunks = K / TBK;

  const float* gA = A + (size_t)bm * K;
  const float* gB = B + (size_t)bn * K;
  const uint32_t sbase = smem_u32(sm);

  auto load_chunk = [&](int c) {
    const int s = c % TSTAGES;
    const uint32_t sa = sbase + s * STAGE_FLOATS * 4;
    const uint32_t sbb = sa + TILE_FLOATS * 4;
    const int k0 = c * TBK;
#pragma unroll
    for (int i = 0; i < 4; i++) {
      int idx = tid + i * 256;
      int r = idx >> 3, c4 = idx & 7;
      cp_async16(sa + (r * TSTRIDE + c4 * 4) * 4, gA + (size_t)r * K + k0 + c4 * 4);
    }
#pragma unroll
    for (int i = 0; i < 4; i++) {
      int idx = tid + i * 256;
      int r = idx >> 3, c4 = idx & 7;
      cp_async16(sbb + (r * TSTRIDE + c4 * 4) * 4, gB + (size_t)r * K + k0 + c4 * 4);
    }
    CP_ASYNC_COMMIT();
  };

  float acc[4][4][4];
#pragma unroll
  for (int mf = 0; mf < 4; mf++)
#pragma unroll
    for (int nf = 0; nf < 4; nf++)
#pragma unroll
      for (int r = 0; r < 4; r++) acc[mf][nf][r] = 0.f;

  load_chunk(0);
  load_chunk(1);

  for (int i = 0; i < nchunks; i++) {
    if (i < nchunks - 1)
      cp_async_wait<1>();
    else
      cp_async_wait<0>();
    __syncthreads();

    if (i + 2 < nchunks) load_chunk(i + 2);

    const float* As = sm + (i % TSTAGES) * STAGE_FLOATS;
    const float* Bs = As + TILE_FLOATS;

#pragma unroll
    for (int k8 = 0; k8 < 4; k8++) {
      uint32_t a[4][4], b[4][2];
#pragma unroll
      for (int mf = 0; mf < 4; mf++) {
        const float* ap = As + (wm * 64 + mf * 16 + gid) * TSTRIDE + k8 * 8 + tg;
        a[mf][0] = f2tf32(ap[0]);
        a[mf][1] = f2tf32(ap[8 * TSTRIDE]);
        a[mf][2] = f2tf32(ap[4]);
        a[mf][3] = f2tf32(ap[8 * TSTRIDE + 4]);
      }
#pragma unroll
      for (int nf = 0; nf < 4; nf++) {
        const float* bp = Bs + (wn * 32 + nf * 8 + gid) * TSTRIDE + k8 * 8 + tg;
        b[nf][0] = f2tf32(bp[0]);
        b[nf][1] = f2tf32(bp[4]);
      }
#pragma unroll
      for (int mf = 0; mf < 4; mf++)
#pragma unroll
        for (int nf = 0; nf < 4; nf++) mma_tf32(acc[mf][nf], a[mf], b[nf]);
    }
    __syncthreads();
  }

#pragma unroll
  for (int mf = 0; mf < 4; mf++) {
    int row0 = bm + wm * 64 + mf * 16 + gid;
#pragma unroll
    for (int nf = 0; nf < 4; nf++) {
      int col = bn + wn * 32 + nf * 8 + 2 * tg;
      *(float2*)(C + (size_t)row0 * N + col) =
          make_float2(acc[mf][nf][0], acc[mf][nf][1]);
      *(float2*)(C + (size_t)(row0 + 8) * N + col) =
          make_float2(acc[mf][nf][2], acc[mf][nf][3]);
    }
  }
}

// ===========================================================================
// fp32 SGEMM (KV projection: N=256, fp32-exact for K/V outputs)
// ===========================================================================
__global__ void __launch_bounds__(256) sgemm_nt_kernel(
    const float* __restrict__ A, const float* __restrict__ B,
    float* __restrict__ C, int M, int N, int K) {
  __shared__ float As[8][128];
  __shared__ float Bs[8][128];
  const int tid = threadIdx.x;
  const int bm = blockIdx.y * 128;
  const int bn = blockIdx.x * 128;
  const int ty = tid >> 4;
  const int tx = tid & 15;
  const int lrow = tid >> 1;
  const int lcol = (tid & 1) * 4;

  float acc[8][8];
#pragma unroll
  for (int i = 0; i < 8; i++)
#pragma unroll
    for (int j = 0; j < 8; j++) acc[i][j] = 0.f;

  for (int k0 = 0; k0 < K; k0 += 8) {
    float4 av = *(const float4*)(A + (size_t)(bm + lrow) * K + k0 + lcol);
    As[lcol + 0][lrow] = av.x;
    As[lcol + 1][lrow] = av.y;
    As[lcol + 2][lrow] = av.z;
    As[lcol + 3][lrow] = av.w;
    {
      int kk = tid >> 5;
      int nn = (tid & 31) * 4;
      *(float4*)&Bs[kk][nn] = *(const float4*)(B + (size_t)(k0 + kk) * N + bn + nn);
    }
    __syncthreads();
#pragma unroll
    for (int kk = 0; kk < 8; kk++) {
      float4 a0 = *(float4*)&As[kk][ty * 4];
      float4 a1 = *(float4*)&As[kk][64 + ty * 4];
      float4 b0 = *(float4*)&Bs[kk][tx * 4];
      float4 b1 = *(float4*)&Bs[kk][64 + tx * 4];
      float ar[8] = {a0.x, a0.y, a0.z, a0.w, a1.x, a1.y, a1.z, a1.w};
      float br[8] = {b0.x, b0.y, b0.z, b0.w, b1.x, b1.y, b1.z, b1.w};
#pragma unroll
      for (int i = 0; i < 8; i++)
#pragma unroll
        for (int j = 0; j < 8; j++) acc[i][j] = fmaf(ar[i], br[j], acc[i][j]);
    }
    __syncthreads();
  }

#pragma unroll
  for (int i = 0; i < 8; i++) {
    int row = bm + ty * 4 + (i & 3) + ((i >= 4) ? 64 : 0);
    *(float4*)(C + (size_t)row * N + bn + tx * 4) =
        make_float4(acc[i][0], acc[i][1], acc[i][2], acc[i][3]);
    *(float4*)(C + (size_t)row * N + bn + 64 + tx * 4) =
        make_float4(acc[i][4], acc[i][5], acc[i][6], acc[i][7]);
  }
}

// ---------------------------------------------------------------------------
// RoPE on Q, in-place. Output is tf32-rounded (Q only feeds tf32 attention).
// ---------------------------------------------------------------------------
__global__ void rope_q_kernel(float* __restrict__ Q, const int* __restrict__ past) {
  const int tok = blockIdx.x;
  const int s = tok % NS;
  const int pos = past[0] + s;
  const int t = threadIdx.x;
  const int h = t >> 6;
  const int i = t & 63;
  float fr = 1.0f / powf(10000.0f, (float)(2 * i) / 128.0f);
  float ang = (float)pos * fr;
  float sn, cs;
  sincosf(ang, &sn, &cs);
  float* q = Q + (size_t)tok * ND + h * NDH;
  float x1 = q[i];
  float x2 = q[i + 64];
  q[i]      = f2tf32f(x1 * cs - x2 * sn);
  q[i + 64] = f2tf32f(x2 * cs + x1 * sn);
}

// ---------------------------------------------------------------------------
// Split KV into exact K/V outputs; roped K scratch is tf32-rounded.
// ---------------------------------------------------------------------------
__global__ void split_rope_k_kernel(const float* __restrict__ KV,
                                    float* __restrict__ Kout,
                                    float* __restrict__ Vout,
                                    float* __restrict__ Kr) {
  const int tok = blockIdx.x;
  const int s = tok % NS;
  const int t = threadIdx.x;
  const float* kv = KV + (size_t)tok * 256;
  Kout[(size_t)tok * NDH + t] = kv[t];
  Vout[(size_t)tok * NDH + t] = kv[128 + t];
  if (t < 64) {
    float fr = 1.0f / powf(10000.0f, (float)(2 * t) / 128.0f);
    float ang = (float)s * fr;
    float sn, cs;
    sincosf(ang, &sn, &cs);
    float x1 = kv[t];
    float x2 = kv[t + 64];
    Kr[(size_t)tok * NDH + t]      = f2tf32f(x1 * cs - x2 * sn);
    Kr[(size_t)tok * NDH + t + 64] = f2tf32f(x2 * cs + x1 * sn);
  }
}

// ===========================================================================
// Tensor-core flash attention (causal, MQA), tf32 mma.sync.
// Block: 128 q-rows x head x batch. 256 threads = 8 warps x 16 rows.
// K tiles of 64 keys. Smem (floats):
//   qs[128][132]   roped Q (tf32 bits)
//   ks[64][132]    roped K (tf32 bits)
//   vt[128][68]    V transposed [dh][key] (tf32 bits)
//   ps[128][68]    P tile (tf32 bits)
// ===========================================================================
#define AQ_STR 132
#define AV_STR 68
#define QS_OFF 0
#define KS_OFF (128 * AQ_STR)                 // 16896
#define VT_OFF (KS_OFF + 64 * AQ_STR)         // 25344
#define PS_OFF (VT_OFF + 128 * AV_STR)        // 34048
#define ATTN_SMEM ((PS_OFF + 128 * AV_STR) * 4)  // 171008 bytes

__global__ void __launch_bounds__(256, 1) attn_mma_kernel(
    const float* __restrict__ Q, const float* __restrict__ Kr,
    const float* __restrict__ KV, float* __restrict__ O,
    const int* __restrict__ past) {
  extern __shared__ float sm[];
  uint32_t* smu = (uint32_t*)sm;
  const uint32_t sbase = smem_u32(sm);

  const int qt = (int)gridDim.x - 1 - (int)blockIdx.x;  // heavy tiles first
  const int h = blockIdx.y;
  const int b = blockIdx.z;
  const int tid = threadIdx.x;
  const int w = tid >> 5;
  const int lane = tid & 31;
  const int gid = lane >> 2;
  const int tg = lane & 3;
  const int q0 = qt * 128;
  const int pl = past[0];
  const float scale = 0.08838834764831845f;  // 1/sqrt(128)

  // Load Q tile (tf32 bits already) via cp.async
#pragma unroll
  for (int i = 0; i < 16; i++) {
    int idx = tid + i * 256;
    int r = idx >> 5, c4 = idx & 31;
    cp_async16(sbase + (QS_OFF + r * AQ_STR + c4 * 4) * 4,
               Q + ((size_t)(b * NS + q0 + r)) * ND + h * NDH + c4 * 4);
  }
  CP_ASYNC_COMMIT();

  float oacc[16][4];
#pragma unroll
  for (int nf = 0; nf < 16; nf++)
#pragma unroll
    for (int r = 0; r < 4; r++) oacc[nf][r] = 0.f;
  float mrow0 = -1e30f, mrow1 = -1e30f;
  float lrow0 = 0.f, lrow1 = 0.f;

  const int r0 = w * 16 + gid;  // local row of this thread's first row
  const int nkt = 2 * qt + 2;

  for (int kt = 0; kt < nkt; kt++) {
    __syncthreads();  // everyone done with previous ks/vt

    // K tile (tf32 bits) via cp.async
#pragma unroll
    for (int i = 0; i < 8; i++) {
      int idx = tid + i * 256;
      int r = idx >> 5, c4 = idx & 31;
      cp_async16(sbase + (KS_OFF + r * AQ_STR + c4 * 4) * 4,
                 Kr + ((size_t)(b * NS + kt * 64 + r)) * NDH + c4 * 4);
    }
    CP_ASYNC_COMMIT();

    // V tile: LDG + tf32 cvt + transposed STS  vt[dh][key]
#pragma unroll
    for (int i = 0; i < 8; i++) {
      int idx = tid + i * 256;
      int r = idx >> 5, c4 = idx & 31;  // key r, dh chunk c4
      float4 v = *(const float4*)(KV + ((size_t)(b * NS + kt * 64 + r)) * 256 +
                                  128 + c4 * 4);
      smu[VT_OFF + (c4 * 4 + 0) * AV_STR + r] = f2tf32(v.x);
      smu[VT_OFF + (c4 * 4 + 1) * AV_STR + r] = f2tf32(v.y);
      smu[VT_OFF + (c4 * 4 + 2) * AV_STR + r] = f2tf32(v.z);
      smu[VT_OFF + (c4 * 4 + 3) * AV_STR + r] = f2tf32(v.w);
    }
    cp_async_wait<0>();
    __syncthreads();

    // ---- S = Q K^T ----
    float sacc[8][4];
#pragma unroll
    for (int nf = 0; nf < 8; nf++)
#pragma unroll
      for (int r = 0; r < 4; r++) sacc[nf][r] = 0.f;

#pragma unroll
    for (int k8 = 0; k8 < 16; k8++) {
      uint32_t a[4];
      const int ab = QS_OFF + r0 * AQ_STR + k8 * 8 + tg;
      a[0] = smu[ab];
      a[1] = smu[ab + 8 * AQ_STR];
      a[2] = smu[ab + 4];
      a[3] = smu[ab + 8 * AQ_STR + 4];
#pragma unroll
      for (int nf = 0; nf < 8; nf++) {
        uint32_t bfr[2];
        const int bb = KS_OFF + (nf * 8 + gid) * AQ_STR + k8 * 8 + tg;
        bfr[0] = smu[bb];
        bfr[1] = smu[bb + 4];
        mma_tf32(sacc[nf], a, bfr);
      }
    }

    // ---- scale + causal mask ----
    const bool partial = ((kt + 1) * 64 - 1) > (q0 + pl);
    if (partial) {
      const int L0 = q0 + pl + r0;
      const int L1 = L0 + 8;
      const int jb = kt * 64 + 2 * tg;
#pragma unroll
      for (int nf = 0; nf < 8; nf++) {
        int j0 = jb + nf * 8;
        sacc[nf][0] = (j0 <= L0) ? sacc[nf][0] * scale : -1e30f;
        sacc[nf][1] = (j0 + 1 <= L0) ? sacc[nf][1] * scale : -1e30f;
        sacc[nf][2] = (j0 <= L1) ? sacc[nf][2] * scale : -1e30f;
        sacc[nf][3] = (j0 + 1 <= L1) ? sacc[nf][3] * scale : -1e30f;
      }
    } else {
#pragma unroll
      for (int nf = 0; nf < 8; nf++)
#pragma unroll
        for (int r = 0; r < 4; r++) sacc[nf][r] *= scale;
    }

    // ---- online softmax (quad reductions over tg lanes) ----
    float m0 = -1e30f, m1 = -1e30f;
#pragma unroll
    for (int nf = 0; nf < 8; nf++) {
      m0 = fmaxf(m0, fmaxf(sacc[nf][0], sacc[nf][1]));
      m1 = fmaxf(m1, fmaxf(sacc[nf][2], sacc[nf][3]));
    }
    m0 = fmaxf(m0, __shfl_xor_sync(0xffffffffu, m0, 1));
    m0 = fmaxf(m0, __shfl_xor_sync(0xffffffffu, m0, 2));
    m1 = fmaxf(m1, __shfl_xor_sync(0xffffffffu, m1, 1));
    m1 = fmaxf(m1, __shfl_xor_sync(0xffffffffu, m1, 2));

    const float mn0 = fmaxf(mrow0, m0);
    const float mn1 = fmaxf(mrow1, m1);
    const float al0 = __expf(mrow0 - mn0);
    const float al1 = __expf(mrow1 - mn1);
    mrow0 = mn0;
    mrow1 = mn1;

    float s0 = 0.f, s1 = 0.f;
#pragma unroll
    for (int nf = 0; nf < 8; nf++) {
      float p00 = __expf(sacc[nf][0] - mn0);
      float p01 = __expf(sacc[nf][1] - mn0);
      float p10 = __expf(sacc[nf][2] - mn1);
      float p11 = __expf(sacc[nf][3] - mn1);
      s0 += p00 + p01;
      s1 += p10 + p11;
      const int pb = PS_OFF + r0 * AV_STR + nf * 8 + 2 * tg;
      *(float2*)&sm[pb] =
          make_float2(__uint_as_float(f2tf32(p00)), __uint_as_float(f2tf32(p01)));
      *(float2*)&sm[pb + 8 * AV_STR] =
          make_float2(__uint_as_float(f2tf32(p10)), __uint_as_float(f2tf32(p11)));
    }
    s0 += __shfl_xor_sync(0xffffffffu, s0, 1);
    s0 += __shfl_xor_sync(0xffffffffu, s0, 2);
    s1 += __shfl_xor_sync(0xffffffffu, s1, 1);
    s1 += __shfl_xor_sync(0xffffffffu, s1, 2);
    lrow0 = lrow0 * al0 + s0;
    lrow1 = lrow1 * al1 + s1;

#pragma unroll
    for (int nf = 0; nf < 16; nf++) {
      oacc[nf][0] *= al0;
      oacc[nf][1] *= al0;
      oacc[nf][2] *= al1;
      oacc[nf][3] *= al1;
    }

    // ---- O += P V  (warp-private P rows; no extra sync needed) ----
#pragma unroll
    for (int k8 = 0; k8 < 8; k8++) {
      uint32_t a[4];
      const int ab = PS_OFF + r0 * AV_STR + k8 * 8 + tg;
      a[0] = smu[ab];
      a[1] = smu[ab + 8 * AV_STR];
      a[2] = smu[ab + 4];
      a[3] = smu[ab + 8 * AV_STR + 4];
#pragma unroll
      for (int nf = 0; nf < 16; nf++) {
        uint32_t bfr[2];
        const int bb = VT_OFF + (nf * 8 + gid) * AV_STR + k8 * 8 + tg;
        bfr[0] = smu[bb];
        bfr[1] = smu[bb + 4];
        mma_tf32(oacc[nf], a, bfr);
      }
    }
  }

  // ---- epilogue: normalize, write O ----
  const float inv0 = 1.0f / lrow0;
  const float inv1 = 1.0f / lrow1;
  const size_t grow0 = (size_t)(b * NS + q0 + r0) * ND + h * NDH;
  const size_t grow1 = grow0 + (size_t)8 * ND;
#pragma unroll
  for (int nf = 0; nf < 16; nf++) {
    int col = nf * 8 + 2 * tg;
    *(float2*)(O + grow0 + col) =
        make_float2(oacc[nf][0] * inv0, oacc[nf][1] * inv0);
    *(float2*)(O + grow1 + col) =
        make_float2(oacc[nf][2] * inv1, oacc[nf][3] * inv1);
  }
}

// ---------------------------------------------------------------------------
extern "C" void kernel_launch(void* const* d_in, const int* in_sizes, int n_in,
                              void* d_out, int out_size) {
  const float* x   = (const float*)d_in[0];
  const float* wq  = (const float*)d_in[1];
  const float* wkv = (const float*)d_in[2];
  const float* wo  = (const float*)d_in[3];
  const int*  past = (const int*)d_in[4];

  float* out  = (float*)d_out;
  float* Kout = out + (size_t)NTOK * ND;
  float* Vout = Kout + (size_t)NTOK * NDH;

  float *Qs, *Os, *KVs, *Krs;
  cudaGetSymbolAddress((void**)&Qs, g_Q);
  cudaGetSymbolAddress((void**)&Os, g_O);
  cudaGetSymbolAddress((void**)&KVs, g_KV);
  cudaGetSymbolAddress((void**)&Krs, g_Kr);

  cudaFuncSetAttribute(tf32_mma_gemm,
                       cudaFuncAttributeMaxDynamicSharedMemorySize, MMA_SMEM);
  cudaFuncSetAttribute(attn_mma_kernel,
                       cudaFuncAttributeMaxDynamicSharedMemorySize, ATTN_SMEM);

  // Q = x @ wq.T  (tf32 mma.sync)
  tf32_mma_gemm<<<dim3(ND / TBN, NTOK / TBM), 256, MMA_SMEM>>>(
      x, wq, Qs, NTOK, ND, ND);
  // KV = x @ wkv  (fp32 exact — K,V are outputs)
  sgemm_nt_kernel<<<dim3(2, NTOK / 128), 256>>>(x, wkv, KVs, NTOK, 256, ND);
  // RoPE Q in place (writes tf32-rounded)
  rope_q_kernel<<<NTOK, 1024>>>(Qs, past);
  // Split K/V to outputs (exact), rope K into scratch (tf32-rounded)
  split_rope_k_kernel<<<NTOK, 128>>>(KVs, Kout, Vout, Krs);
  // Flash attention (tf32 tensor cores)
  attn_mma_kernel<<<dim3(NS / 128, NH, NB), 256, ATTN_SMEM>>>(
      Qs, Krs, KVs, Os, past);
  // out = O @ wo.T  (tf32 mma.sync)
  tf32_mma_gemm<<<dim3(ND / TBN, NTOK / TBM), 256, MMA_SMEM>>>(
      Os, wo, out, NTOK, ND, ND);
}

// round 6
// speedup vs baseline: 3.3574x; 1.3959x over previous
#include <cuda_runtime.h>
#include <cstdint>

#define NB   2
#define NS   2048
#define ND   2048
#define NH   16
#define NDH  128
#define NTOK (NB * NS)

// Scratch (device globals: no allocation allowed in kernel_launch)
__device__ float g_Q  [(size_t)NTOK * ND];      // roped Q (tf32-rounded)
__device__ float g_O  [(size_t)NTOK * ND];      // attention out (tf32-rounded)
__device__ float g_KV [(size_t)NTOK * 2 * NDH]; // KV projection result
__device__ float g_Kr [(size_t)NTOK * NDH];     // roped K (tf32-rounded)
__device__ float g_Vr [(size_t)NTOK * NDH];     // V (tf32-rounded)
__device__ float g_xr [(size_t)NTOK * ND];      // x  (tf32-rounded)
__device__ float g_wqr[(size_t)ND * ND];        // wq (tf32-rounded)
__device__ float g_wor[(size_t)ND * ND];        // wo (tf32-rounded)
__device__ float g_wkvT[(size_t)256 * ND];      // wkv^T (tf32-rounded) [256][2048]

// ===========================================================================
// PTX helpers (portable sm_80+ subset)
// ===========================================================================
__device__ __forceinline__ uint32_t smem_u32(const void* p) {
  uint32_t a;
  asm("{ .reg .u64 t; cvta.to.shared.u64 t, %1; cvt.u32.u64 %0, t; }"
      : "=r"(a) : "l"(p));
  return a;
}
__device__ __forceinline__ void cp_async16(uint32_t dst, const void* src) {
  asm volatile("cp.async.cg.shared.global [%0], [%1], 16;" ::"r"(dst), "l"(src));
}
#define CP_ASYNC_COMMIT() asm volatile("cp.async.commit_group;" ::: "memory")
template <int N>
__device__ __forceinline__ void cp_async_wait() {
  asm volatile("cp.async.wait_group %0;" ::"n"(N) : "memory");
}
__device__ __forceinline__ uint32_t f2tf32(float x) {
  uint32_t r;
  asm("cvt.rna.tf32.f32 %0, %1;" : "=r"(r) : "f"(x));
  return r;
}
__device__ __forceinline__ float f2tf32f(float x) {
  return __uint_as_float(f2tf32(x));
}
__device__ __forceinline__ void mma_tf32(float* c, const uint32_t* a,
                                         const uint32_t* b) {
  asm volatile(
      "mma.sync.aligned.m16n8k8.row.col.f32.tf32.tf32.f32 "
      "{%0,%1,%2,%3}, {%4,%5,%6,%7}, {%8,%9}, {%0,%1,%2,%3};"
      : "+f"(c[0]), "+f"(c[1]), "+f"(c[2]), "+f"(c[3])
      : "r"(a[0]), "r"(a[1]), "r"(a[2]), "r"(a[3]), "r"(b[0]), "r"(b[1]));
}

// ===========================================================================
// tf32 mma.sync GEMM: C[M,N] = A[M,K] @ B[N,K]^T. Operands PRE-ROUNDED tf32.
// Tile 128x128x32, 256 threads (8 warps, 2x4), warp tile 64x32, 3 stages.
// ===========================================================================
#define TBM 128
#define TBN 128
#define TBK 32
#define TSTRIDE 36
#define TILE_FLOATS (TBM * TSTRIDE)
#define STAGE_FLOATS (2 * TILE_FLOATS)
#define TSTAGES 3
#define MMA_SMEM (TSTAGES * STAGE_FLOATS * 4)

__global__ void __launch_bounds__(256, 1)
tf32_mma_gemm(const float* __restrict__ A, const float* __restrict__ B,
              float* __restrict__ C, int M, int N, int K) {
  extern __shared__ float sm[];
  const uint32_t* smu = (const uint32_t*)sm;
  const int tid = threadIdx.x;
  const int wid = tid >> 5;
  const int lane = tid & 31;
  const int gid = lane >> 2;
  const int tg = lane & 3;
  const int wm = wid & 1;
  const int wn = wid >> 1;
  const int bm = blockIdx.y * TBM;
  const int bn = blockIdx.x * TBN;
  const int nchunks = K / TBK;

  const float* gA = A + (size_t)bm * K;
  const float* gB = B + (size_t)bn * K;
  const uint32_t sbase = smem_u32(sm);

  auto load_chunk = [&](int c) {
    const int s = c % TSTAGES;
    const uint32_t sa = sbase + s * STAGE_FLOATS * 4;
    const uint32_t sbb = sa + TILE_FLOATS * 4;
    const int k0 = c * TBK;
#pragma unroll
    for (int i = 0; i < 4; i++) {
      int idx = tid + i * 256;
      int r = idx >> 3, c4 = idx & 7;
      cp_async16(sa + (r * TSTRIDE + c4 * 4) * 4, gA + (size_t)r * K + k0 + c4 * 4);
    }
#pragma unroll
    for (int i = 0; i < 4; i++) {
      int idx = tid + i * 256;
      int r = idx >> 3, c4 = idx & 7;
      cp_async16(sbb + (r * TSTRIDE + c4 * 4) * 4, gB + (size_t)r * K + k0 + c4 * 4);
    }
    CP_ASYNC_COMMIT();
  };

  float acc[4][4][4];
#pragma unroll
  for (int mf = 0; mf < 4; mf++)
#pragma unroll
    for (int nf = 0; nf < 4; nf++)
#pragma unroll
      for (int r = 0; r < 4; r++) acc[mf][nf][r] = 0.f;

  load_chunk(0);
  load_chunk(1);

  for (int i = 0; i < nchunks; i++) {
    if (i < nchunks - 1)
      cp_async_wait<1>();
    else
      cp_async_wait<0>();
    __syncthreads();

    if (i + 2 < nchunks) load_chunk(i + 2);

    const uint32_t* As = smu + (i % TSTAGES) * STAGE_FLOATS;
    const uint32_t* Bs = As + TILE_FLOATS;

#pragma unroll
    for (int k8 = 0; k8 < 4; k8++) {
      uint32_t a[4][4], b[4][2];
#pragma unroll
      for (int mf = 0; mf < 4; mf++) {
        const uint32_t* ap = As + (wm * 64 + mf * 16 + gid) * TSTRIDE + k8 * 8 + tg;
        a[mf][0] = ap[0];
        a[mf][1] = ap[8 * TSTRIDE];
        a[mf][2] = ap[4];
        a[mf][3] = ap[8 * TSTRIDE + 4];
      }
#pragma unroll
      for (int nf = 0; nf < 4; nf++) {
        const uint32_t* bp = Bs + (wn * 32 + nf * 8 + gid) * TSTRIDE + k8 * 8 + tg;
        b[nf][0] = bp[0];
        b[nf][1] = bp[4];
      }
#pragma unroll
      for (int mf = 0; mf < 4; mf++)
#pragma unroll
        for (int nf = 0; nf < 4; nf++) mma_tf32(acc[mf][nf], a[mf], b[nf]);
    }
    __syncthreads();
  }

#pragma unroll
  for (int mf = 0; mf < 4; mf++) {
    int row0 = bm + wm * 64 + mf * 16 + gid;
#pragma unroll
    for (int nf = 0; nf < 4; nf++) {
      int col = bn + wn * 32 + nf * 8 + 2 * tg;
      *(float2*)(C + (size_t)row0 * N + col) =
          make_float2(acc[mf][nf][0], acc[mf][nf][1]);
      *(float2*)(C + (size_t)(row0 + 8) * N + col) =
          make_float2(acc[mf][nf][2], acc[mf][nf][3]);
    }
  }
}

// ---------------------------------------------------------------------------
// Elementwise tf32 rounding (float4 vectorized).
// ---------------------------------------------------------------------------
__global__ void round_tf32_kernel(const float* __restrict__ in,
                                  float* __restrict__ out, int n4) {
  int i = blockIdx.x * 256 + threadIdx.x;
  if (i < n4) {
    float4 v = ((const float4*)in)[i];
    v.x = f2tf32f(v.x);
    v.y = f2tf32f(v.y);
    v.z = f2tf32f(v.z);
    v.w = f2tf32f(v.w);
    ((float4*)out)[i] = v;
  }
}

// ---------------------------------------------------------------------------
// Transpose + round: wkv [2048][256] -> wkvT [256][2048] (tf32-rounded).
// ---------------------------------------------------------------------------
__global__ void transpose_round_kernel(const float* __restrict__ in,
                                       float* __restrict__ out) {
  __shared__ float t[32][33];
  const int k0 = blockIdx.x * 32;
  const int n0 = blockIdx.y * 32;
  const int tx = threadIdx.x;
  const int ty = threadIdx.y;
#pragma unroll
  for (int j = 0; j < 4; j++)
    t[ty + 8 * j][tx] = in[(size_t)(k0 + ty + 8 * j) * 256 + n0 + tx];
  __syncthreads();
#pragma unroll
  for (int j = 0; j < 4; j++)
    out[(size_t)(n0 + ty + 8 * j) * 2048 + k0 + tx] = f2tf32f(t[tx][ty + 8 * j]);
}

// ---------------------------------------------------------------------------
// RoPE on Q, in-place (tf32-rounded output).
// ---------------------------------------------------------------------------
__global__ void rope_q_kernel(float* __restrict__ Q, const int* __restrict__ past) {
  const int tok = blockIdx.x;
  const int s = tok % NS;
  const int pos = past[0] + s;
  const int t = threadIdx.x;
  const int h = t >> 6;
  const int i = t & 63;
  float fr = 1.0f / powf(10000.0f, (float)(2 * i) / 128.0f);
  float ang = (float)pos * fr;
  float sn, cs;
  sincosf(ang, &sn, &cs);
  float* q = Q + (size_t)tok * ND + h * NDH;
  float x1 = q[i];
  float x2 = q[i + 64];
  q[i]      = f2tf32f(x1 * cs - x2 * sn);
  q[i + 64] = f2tf32f(x2 * cs + x1 * sn);
}

// ---------------------------------------------------------------------------
// Split KV: exact K/V to outputs, roped K + rounded V to scratch.
// ---------------------------------------------------------------------------
__global__ void split_rope_k_kernel(const float* __restrict__ KV,
                                    float* __restrict__ Kout,
                                    float* __restrict__ Vout,
                                    float* __restrict__ Kr,
                                    float* __restrict__ Vr) {
  const int tok = blockIdx.x;
  const int s = tok % NS;
  const int t = threadIdx.x;
  const float* kv = KV + (size_t)tok * 256;
  float vv = kv[128 + t];
  Kout[(size_t)tok * NDH + t] = kv[t];
  Vout[(size_t)tok * NDH + t] = vv;
  Vr[(size_t)tok * NDH + t] = f2tf32f(vv);
  if (t < 64) {
    float fr = 1.0f / powf(10000.0f, (float)(2 * t) / 128.0f);
    float ang = (float)s * fr;
    float sn, cs;
    sincosf(ang, &sn, &cs);
    float x1 = kv[t];
    float x2 = kv[t + 64];
    Kr[(size_t)tok * NDH + t]      = f2tf32f(x1 * cs - x2 * sn);
    Kr[(size_t)tok * NDH + t + 64] = f2tf32f(x2 * cs + x1 * sn);
  }
}

// ===========================================================================
// Tensor-core flash attention, tf32 mma.sync, pipelined K/V double buffer.
// Block: 128 q-rows x head x batch, 256 threads = 8 warps x 16 rows.
// Smem (words): qs[128][132] | ks[2][64][132] | vraw[2][64][136]
// P never touches smem: C-layout -> A-layout via intra-quad shuffles.
// ===========================================================================
#define AQ_STR 132
#define AVR_STR 136
#define QS_OFF 0
#define KS_OFF (128 * AQ_STR)                    // 16896
#define KS_SZ (64 * AQ_STR)                      // 8448
#define VR_OFF (KS_OFF + 2 * KS_SZ)              // 33792
#define VR_SZ (64 * AVR_STR)                     // 8704
#define ATTN_SMEM ((VR_OFF + 2 * VR_SZ) * 4)     // 204800 bytes

__global__ void __launch_bounds__(256, 1) attn_mma_kernel(
    const float* __restrict__ Q, const float* __restrict__ Kr,
    const float* __restrict__ Vr, float* __restrict__ O,
    const int* __restrict__ past) {
  extern __shared__ float sm[];
  uint32_t* smu = (uint32_t*)sm;
  const uint32_t sbase = smem_u32(sm);

  const int qt = (int)gridDim.x - 1 - (int)blockIdx.x;  // heavy tiles first
  const int h = blockIdx.y;
  const int b = blockIdx.z;
  const int tid = threadIdx.x;
  const int w = tid >> 5;
  const int lane = tid & 31;
  const int gid = lane >> 2;
  const int tg = lane & 3;
  const int q0 = qt * 128;
  const int pl = past[0];
  const float scale = 0.08838834764831845f;  // 1/sqrt(128)
  const int nkt = 2 * qt + 2;

  auto load_tile = [&](int kt) {
    const int s = kt & 1;
    const uint32_t ksb = sbase + (KS_OFF + s * KS_SZ) * 4;
    const uint32_t vrb = sbase + (VR_OFF + s * VR_SZ) * 4;
    const size_t tok0 = (size_t)(b * NS) + kt * 64;
#pragma unroll
    for (int i = 0; i < 8; i++) {
      int idx = tid + i * 256;
      int r = idx >> 5, c4 = idx & 31;
      cp_async16(ksb + (r * AQ_STR + c4 * 4) * 4, Kr + (tok0 + r) * NDH + c4 * 4);
    }
#pragma unroll
    for (int i = 0; i < 8; i++) {
      int idx = tid + i * 256;
      int r = idx >> 5, c4 = idx & 31;
      cp_async16(vrb + (r * AVR_STR + c4 * 4) * 4, Vr + (tok0 + r) * NDH + c4 * 4);
    }
    CP_ASYNC_COMMIT();
  };

  // Prologue: Q tile + tile 0 in one group.
#pragma unroll
  for (int i = 0; i < 16; i++) {
    int idx = tid + i * 256;
    int r = idx >> 5, c4 = idx & 31;
    cp_async16(sbase + (QS_OFF + r * AQ_STR + c4 * 4) * 4,
               Q + ((size_t)(b * NS + q0 + r)) * ND + h * NDH + c4 * 4);
  }
  load_tile(0);  // commits group 0 (includes Q)

  float oacc[16][4];
#pragma unroll
  for (int nf = 0; nf < 16; nf++)
#pragma unroll
    for (int r = 0; r < 4; r++) oacc[nf][r] = 0.f;
  float mrow0 = -1e30f, mrow1 = -1e30f;
  float lrow0 = 0.f, lrow1 = 0.f;

  const int r0 = w * 16 + gid;
  const int srcA = (lane & ~3) | (tg >> 1);
  const int srcB = (lane & ~3) | ((tg >> 1) + 2);

  for (int kt = 0; kt < nkt; kt++) {
    if (kt + 1 < nkt) {
      load_tile(kt + 1);
      cp_async_wait<1>();
    } else {
      cp_async_wait<0>();
    }
    __syncthreads();

    const uint32_t* ksb = smu + KS_OFF + (kt & 1) * KS_SZ;
    const uint32_t* vrb = smu + VR_OFF + (kt & 1) * VR_SZ;

    // ---- S = Q K^T ----
    float sacc[8][4];
#pragma unroll
    for (int nf = 0; nf < 8; nf++)
#pragma unroll
      for (int r = 0; r < 4; r++) sacc[nf][r] = 0.f;

#pragma unroll
    for (int k8 = 0; k8 < 16; k8++) {
      uint32_t a[4];
      const uint32_t* ap = smu + QS_OFF + r0 * AQ_STR + k8 * 8 + tg;
      a[0] = ap[0];
      a[1] = ap[8 * AQ_STR];
      a[2] = ap[4];
      a[3] = ap[8 * AQ_STR + 4];
#pragma unroll
      for (int nf = 0; nf < 8; nf++) {
        uint32_t bf[2];
        const uint32_t* bp = ksb + (nf * 8 + gid) * AQ_STR + k8 * 8 + tg;
        bf[0] = bp[0];
        bf[1] = bp[4];
        mma_tf32(sacc[nf], a, bf);
      }
    }

    // ---- scale + causal mask ----
    const bool partial = ((kt + 1) * 64 - 1) > (q0 + pl);
    if (partial) {
      const int L0 = q0 + pl + r0;
      const int L1 = L0 + 8;
      const int jb = kt * 64 + 2 * tg;
#pragma unroll
      for (int nf = 0; nf < 8; nf++) {
        int j0 = jb + nf * 8;
        sacc[nf][0] = (j0 <= L0) ? sacc[nf][0] * scale : -1e30f;
        sacc[nf][1] = (j0 + 1 <= L0) ? sacc[nf][1] * scale : -1e30f;
        sacc[nf][2] = (j0 <= L1) ? sacc[nf][2] * scale : -1e30f;
        sacc[nf][3] = (j0 + 1 <= L1) ? sacc[nf][3] * scale : -1e30f;
      }
    } else {
#pragma unroll
      for (int nf = 0; nf < 8; nf++)
#pragma unroll
        for (int r = 0; r < 4; r++) sacc[nf][r] *= scale;
    }

    // ---- online softmax ----
    float m0 = -1e30f, m1 = -1e30f;
#pragma unroll
    for (int nf = 0; nf < 8; nf++) {
      m0 = fmaxf(m0, fmaxf(sacc[nf][0], sacc[nf][1]));
      m1 = fmaxf(m1, fmaxf(sacc[nf][2], sacc[nf][3]));
    }
    m0 = fmaxf(m0, __shfl_xor_sync(0xffffffffu, m0, 1));
    m0 = fmaxf(m0, __shfl_xor_sync(0xffffffffu, m0, 2));
    m1 = fmaxf(m1, __shfl_xor_sync(0xffffffffu, m1, 1));
    m1 = fmaxf(m1, __shfl_xor_sync(0xffffffffu, m1, 2));

    const float mn0 = fmaxf(mrow0, m0);
    const float mn1 = fmaxf(mrow1, m1);
    const float al0 = __expf(mrow0 - mn0);
    const float al1 = __expf(mrow1 - mn1);
    mrow0 = mn0;
    mrow1 = mn1;

    uint32_t pc[8][4];
    float s0 = 0.f, s1 = 0.f;
#pragma unroll
    for (int nf = 0; nf < 8; nf++) {
      float p00 = __expf(sacc[nf][0] - mn0);
      float p01 = __expf(sacc[nf][1] - mn0);
      float p10 = __expf(sacc[nf][2] - mn1);
      float p11 = __expf(sacc[nf][3] - mn1);
      s0 += p00 + p01;
      s1 += p10 + p11;
      pc[nf][0] = f2tf32(p00);
      pc[nf][1] = f2tf32(p01);
      pc[nf][2] = f2tf32(p10);
      pc[nf][3] = f2tf32(p11);
    }
    s0 += __shfl_xor_sync(0xffffffffu, s0, 1);
    s0 += __shfl_xor_sync(0xffffffffu, s0, 2);
    s1 += __shfl_xor_sync(0xffffffffu, s1, 1);
    s1 += __shfl_xor_sync(0xffffffffu, s1, 2);
    lrow0 = lrow0 * al0 + s0;
    lrow1 = lrow1 * al1 + s1;

#pragma unroll
    for (int nf = 0; nf < 16; nf++) {
      oacc[nf][0] *= al0;
      oacc[nf][1] *= al0;
      oacc[nf][2] *= al1;
      oacc[nf][3] *= al1;
    }

    // ---- O += P V : P C-layout -> A-layout via intra-quad shuffles ----
#pragma unroll
    for (int k8 = 0; k8 < 8; k8++) {
      uint32_t t00 = __shfl_sync(0xffffffffu, pc[k8][0], srcA);
      uint32_t t01 = __shfl_sync(0xffffffffu, pc[k8][1], srcA);
      uint32_t t10 = __shfl_sync(0xffffffffu, pc[k8][2], srcA);
      uint32_t t11 = __shfl_sync(0xffffffffu, pc[k8][3], srcA);
      uint32_t u00 = __shfl_sync(0xffffffffu, pc[k8][0], srcB);
      uint32_t u01 = __shfl_sync(0xffffffffu, pc[k8][1], srcB);
      uint32_t u10 = __shfl_sync(0xffffffffu, pc[k8][2], srcB);
      uint32_t u11 = __shfl_sync(0xffffffffu, pc[k8][3], srcB);
      uint32_t a[4];
      a[0] = (tg & 1) ? t01 : t00;
      a[1] = (tg & 1) ? t11 : t10;
      a[2] = (tg & 1) ? u01 : u00;
      a[3] = (tg & 1) ? u11 : u10;
#pragma unroll
      for (int nf = 0; nf < 16; nf++) {
        uint32_t bf[2];
        const uint32_t* bp = vrb + (k8 * 8 + tg) * AVR_STR + nf * 8 + gid;
        bf[0] = bp[0];
        bf[1] = bp[4 * AVR_STR];
        mma_tf32(oacc[nf], a, bf);
      }
    }
    __syncthreads();  // all warps done with this tile's buffers
  }

  // ---- epilogue: normalize, round to tf32 (feeds out-proj), write O ----
  const float inv0 = 1.0f / lrow0;
  const float inv1 = 1.0f / lrow1;
  const size_t grow0 = (size_t)(b * NS + q0 + r0) * ND + h * NDH;
  const size_t grow1 = grow0 + (size_t)8 * ND;
#pragma unroll
  for (int nf = 0; nf < 16; nf++) {
    int col = nf * 8 + 2 * tg;
    *(float2*)(O + grow0 + col) = make_float2(f2tf32f(oacc[nf][0] * inv0),
                                              f2tf32f(oacc[nf][1] * inv0));
    *(float2*)(O + grow1 + col) = make_float2(f2tf32f(oacc[nf][2] * inv1),
                                              f2tf32f(oacc[nf][3] * inv1));
  }
}

// ---------------------------------------------------------------------------
extern "C" void kernel_launch(void* const* d_in, const int* in_sizes, int n_in,
                              void* d_out, int out_size) {
  const float* x   = (const float*)d_in[0];
  const float* wq  = (const float*)d_in[1];
  const float* wkv = (const float*)d_in[2];
  const float* wo  = (const float*)d_in[3];
  const int*  past = (const int*)d_in[4];

  float* out  = (float*)d_out;
  float* Kout = out + (size_t)NTOK * ND;
  float* Vout = Kout + (size_t)NTOK * NDH;

  float *Qs, *Os, *KVs, *Krs, *Vrs, *xr, *wqr, *wor, *wkvT;
  cudaGetSymbolAddress((void**)&Qs, g_Q);
  cudaGetSymbolAddress((void**)&Os, g_O);
  cudaGetSymbolAddress((void**)&KVs, g_KV);
  cudaGetSymbolAddress((void**)&Krs, g_Kr);
  cudaGetSymbolAddress((void**)&Vrs, g_Vr);
  cudaGetSymbolAddress((void**)&xr, g_xr);
  cudaGetSymbolAddress((void**)&wqr, g_wqr);
  cudaGetSymbolAddress((void**)&wor, g_wor);
  cudaGetSymbolAddress((void**)&wkvT, g_wkvT);

  cudaFuncSetAttribute(tf32_mma_gemm,
                       cudaFuncAttributeMaxDynamicSharedMemorySize, MMA_SMEM);
  cudaFuncSetAttribute(attn_mma_kernel,
                       cudaFuncAttributeMaxDynamicSharedMemorySize, ATTN_SMEM);

  // Pre-round operands to tf32 in gmem
  round_tf32_kernel<<<(NTOK * ND / 4 + 255) / 256, 256>>>(x, xr, NTOK * ND / 4);
  round_tf32_kernel<<<(ND * ND / 4 + 255) / 256, 256>>>(wq, wqr, ND * ND / 4);
  round_tf32_kernel<<<(ND * ND / 4 + 255) / 256, 256>>>(wo, wor, ND * ND / 4);
  transpose_round_kernel<<<dim3(ND / 32, 256 / 32), dim3(32, 8)>>>(wkv, wkvT);

  // Q = x @ wq.T
  tf32_mma_gemm<<<dim3(ND / TBN, NTOK / TBM), 256, MMA_SMEM>>>(
      xr, wqr, Qs, NTOK, ND, ND);
  // KV = x @ wkv  (tf32 via transposed weights)
  tf32_mma_gemm<<<dim3(256 / TBN, NTOK / TBM), 256, MMA_SMEM>>>(
      xr, wkvT, KVs, NTOK, 256, ND);
  // RoPE Q in place
  rope_q_kernel<<<NTOK, 1024>>>(Qs, past);
  // Split K/V to outputs, roped K + rounded V scratch
  split_rope_k_kernel<<<NTOK, 128>>>(KVs, Kout, Vout, Krs, Vrs);
  // Flash attention (tf32 tensor cores, pipelined)
  attn_mma_kernel<<<dim3(NS / 128, NH, NB), 256, ATTN_SMEM>>>(
      Qs, Krs, Vrs, Os, past);
  // out = O @ wo.T
  tf32_mma_gemm<<<dim3(ND / TBN, NTOK / TBM), 256, MMA_SMEM>>>(
      Os, wor, out, NTOK, ND, ND);
}

// round 7
// speedup vs baseline: 3.6167x; 1.0772x over previous
#include <cuda_runtime.h>
#include <cstdint>

#define NB   2
#define NS   2048
#define ND   2048
#define NH   16
#define NDH  128
#define NTOK (NB * NS)

// Scratch (device globals: no allocation allowed in kernel_launch)
__device__ float g_Q  [(size_t)NTOK * ND];      // roped Q (tf32, col-interleaved)
__device__ float g_O  [(size_t)NTOK * ND];      // attention out (tf32, col-interleaved)
__device__ float g_KV [(size_t)NTOK * 2 * NDH]; // KV projection result
__device__ float g_Kr [(size_t)NTOK * NDH];     // roped K (tf32, col-interleaved)
__device__ float g_Vr [(size_t)NTOK * NDH];     // V (tf32, plain)
__device__ float g_xr [(size_t)NTOK * ND];      // x  (tf32, plain)
__device__ float g_wqr[(size_t)ND * ND];        // wq (tf32, plain)
__device__ float g_wor[(size_t)ND * ND];        // wo (tf32, col-interleaved)
__device__ float g_wkvT[(size_t)256 * ND];      // wkv^T (tf32, plain)

// ===========================================================================
// Helpers
// ===========================================================================
__device__ __forceinline__ uint32_t smem_u32(const void* p) {
  uint32_t a;
  asm("{ .reg .u64 t; cvta.to.shared.u64 t, %1; cvt.u32.u64 %0, t; }"
      : "=r"(a) : "l"(p));
  return a;
}
__device__ __forceinline__ void cp_async16(uint32_t dst, const void* src) {
  asm volatile("cp.async.cg.shared.global [%0], [%1], 16;" ::"r"(dst), "l"(src));
}
#define CP_ASYNC_COMMIT() asm volatile("cp.async.commit_group;" ::: "memory")
template <int N>
__device__ __forceinline__ void cp_async_wait() {
  asm volatile("cp.async.wait_group %0;" ::"n"(N) : "memory");
}
__device__ __forceinline__ uint32_t f2tf32(float x) {
  uint32_t r;
  asm("cvt.rna.tf32.f32 %0, %1;" : "=r"(r) : "f"(x));
  return r;
}
__device__ __forceinline__ float f2tf32f(float x) {
  return __uint_as_float(f2tf32(x));
}
__device__ __forceinline__ void mma_tf32(float* c, const uint32_t* a,
                                         const uint32_t* b) {
  asm volatile(
      "mma.sync.aligned.m16n8k8.row.col.f32.tf32.tf32.f32 "
      "{%0,%1,%2,%3}, {%4,%5,%6,%7}, {%8,%9}, {%0,%1,%2,%3};"
      : "+f"(c[0]), "+f"(c[1]), "+f"(c[2]), "+f"(c[3])
      : "r"(a[0]), "r"(a[1]), "r"(a[2]), "r"(a[3]), "r"(b[0]), "r"(b[1]));
}
// Column-pair interleave within each 8-col group: fragment words (c, c+4)
// become adjacent, enabling LDS.64 fragment loads.
__device__ __forceinline__ int colmap8(int c) {
  int r = c & 7;
  return (c & ~7) | ((r < 4) ? (r << 1) : (((r - 4) << 1) | 1));
}

// ===========================================================================
// tf32 mma.sync GEMM: C[M,N] = A[M,K] @ B[N,K]^T. Operands PRE-ROUNDED tf32.
// Tile 128x128x32, 256 threads (8 warps, 2x4), warp tile 64x32, 3 stages.
// 2 CTAs/SM (221KB smem total) for latency hiding.
// ===========================================================================
#define TBM 128
#define TBN 128
#define TBK 32
#define TSTRIDE 36
#define TILE_FLOATS (TBM * TSTRIDE)
#define STAGE_FLOATS (2 * TILE_FLOATS)
#define TSTAGES 3
#define MMA_SMEM (TSTAGES * STAGE_FLOATS * 4)

__global__ void __launch_bounds__(256, 2)
tf32_mma_gemm(const float* __restrict__ A, const float* __restrict__ B,
              float* __restrict__ C, int M, int N, int K) {
  extern __shared__ float sm[];
  const uint32_t* smu = (const uint32_t*)sm;
  const int tid = threadIdx.x;
  const int wid = tid >> 5;
  const int lane = tid & 31;
  const int gid = lane >> 2;
  const int tg = lane & 3;
  const int wm = wid & 1;
  const int wn = wid >> 1;
  const int bm = blockIdx.y * TBM;
  const int bn = blockIdx.x * TBN;
  const int nchunks = K / TBK;

  const float* gA = A + (size_t)bm * K;
  const float* gB = B + (size_t)bn * K;
  const uint32_t sbase = smem_u32(sm);

  auto load_chunk = [&](int c) {
    const int s = c % TSTAGES;
    const uint32_t sa = sbase + s * STAGE_FLOATS * 4;
    const uint32_t sbb = sa + TILE_FLOATS * 4;
    const int k0 = c * TBK;
#pragma unroll
    for (int i = 0; i < 4; i++) {
      int idx = tid + i * 256;
      int r = idx >> 3, c4 = idx & 7;
      cp_async16(sa + (r * TSTRIDE + c4 * 4) * 4, gA + (size_t)r * K + k0 + c4 * 4);
    }
#pragma unroll
    for (int i = 0; i < 4; i++) {
      int idx = tid + i * 256;
      int r = idx >> 3, c4 = idx & 7;
      cp_async16(sbb + (r * TSTRIDE + c4 * 4) * 4, gB + (size_t)r * K + k0 + c4 * 4);
    }
    CP_ASYNC_COMMIT();
  };

  float acc[4][4][4];
#pragma unroll
  for (int mf = 0; mf < 4; mf++)
#pragma unroll
    for (int nf = 0; nf < 4; nf++)
#pragma unroll
      for (int r = 0; r < 4; r++) acc[mf][nf][r] = 0.f;

  load_chunk(0);
  load_chunk(1);

  for (int i = 0; i < nchunks; i++) {
    if (i < nchunks - 1)
      cp_async_wait<1>();
    else
      cp_async_wait<0>();
    __syncthreads();

    if (i + 2 < nchunks) load_chunk(i + 2);

    const uint32_t* As = smu + (i % TSTAGES) * STAGE_FLOATS;
    const uint32_t* Bs = As + TILE_FLOATS;

#pragma unroll
    for (int k8 = 0; k8 < 4; k8++) {
      uint32_t a[4][4], b[4][2];
#pragma unroll
      for (int mf = 0; mf < 4; mf++) {
        const uint32_t* ap = As + (wm * 64 + mf * 16 + gid) * TSTRIDE + k8 * 8 + tg;
        a[mf][0] = ap[0];
        a[mf][1] = ap[8 * TSTRIDE];
        a[mf][2] = ap[4];
        a[mf][3] = ap[8 * TSTRIDE + 4];
      }
#pragma unroll
      for (int nf = 0; nf < 4; nf++) {
        const uint32_t* bp = Bs + (wn * 32 + nf * 8 + gid) * TSTRIDE + k8 * 8 + tg;
        b[nf][0] = bp[0];
        b[nf][1] = bp[4];
      }
#pragma unroll
      for (int mf = 0; mf < 4; mf++)
#pragma unroll
        for (int nf = 0; nf < 4; nf++) mma_tf32(acc[mf][nf], a[mf], b[nf]);
    }
    __syncthreads();
  }

#pragma unroll
  for (int mf = 0; mf < 4; mf++) {
    int row0 = bm + wm * 64 + mf * 16 + gid;
#pragma unroll
    for (int nf = 0; nf < 4; nf++) {
      int col = bn + wn * 32 + nf * 8 + 2 * tg;
      *(float2*)(C + (size_t)row0 * N + col) =
          make_float2(acc[mf][nf][0], acc[mf][nf][1]);
      *(float2*)(C + (size_t)(row0 + 8) * N + col) =
          make_float2(acc[mf][nf][2], acc[mf][nf][3]);
    }
  }
}

// ---------------------------------------------------------------------------
// Elementwise tf32 rounding; optional column-pair interleave (for wo).
// ---------------------------------------------------------------------------
__global__ void round_tf32_kernel(const float* __restrict__ in,
                                  float* __restrict__ out, int n4) {
  int i = blockIdx.x * 256 + threadIdx.x;
  if (i < n4) {
    float4 v = ((const float4*)in)[i];
    v.x = f2tf32f(v.x);
    v.y = f2tf32f(v.y);
    v.z = f2tf32f(v.z);
    v.w = f2tf32f(v.w);
    ((float4*)out)[i] = v;
  }
}

__global__ void round_tf32_ilv_kernel(const float* __restrict__ in,
                                      float* __restrict__ out, int n4) {
  int i = blockIdx.x * 256 + threadIdx.x;
  if (i < n4) {
    float4 v = ((const float4*)in)[i];
    int c = i * 4;
    out[colmap8(c + 0)] = f2tf32f(v.x);
    out[colmap8(c + 1)] = f2tf32f(v.y);
    out[colmap8(c + 2)] = f2tf32f(v.z);
    out[colmap8(c + 3)] = f2tf32f(v.w);
  }
}

// ---------------------------------------------------------------------------
// Transpose + round: wkv [2048][256] -> wkvT [256][2048] (tf32).
// ---------------------------------------------------------------------------
__global__ void transpose_round_kernel(const float* __restrict__ in,
                                       float* __restrict__ out) {
  __shared__ float t[32][33];
  const int k0 = blockIdx.x * 32;
  const int n0 = blockIdx.y * 32;
  const int tx = threadIdx.x;
  const int ty = threadIdx.y;
#pragma unroll
  for (int j = 0; j < 4; j++)
    t[ty + 8 * j][tx] = in[(size_t)(k0 + ty + 8 * j) * 256 + n0 + tx];
  __syncthreads();
#pragma unroll
  for (int j = 0; j < 4; j++)
    out[(size_t)(n0 + ty + 8 * j) * 2048 + k0 + tx] = f2tf32f(t[tx][ty + 8 * j]);
}

// ---------------------------------------------------------------------------
// RoPE on Q, in-place, writes tf32-rounded + col-interleaved (per head).
// ---------------------------------------------------------------------------
__global__ void rope_q_kernel(float* __restrict__ Q, const int* __restrict__ past) {
  const int tok = blockIdx.x;
  const int s = tok % NS;
  const int pos = past[0] + s;
  const int t = threadIdx.x;
  const int h = t >> 6;
  const int i = t & 63;
  float fr = 1.0f / powf(10000.0f, (float)(2 * i) / 128.0f);
  float ang = (float)pos * fr;
  float sn, cs;
  sincosf(ang, &sn, &cs);
  float* q = Q + (size_t)tok * ND + h * NDH;
  float x1 = q[i];
  float x2 = q[i + 64];
  __syncthreads();  // in-place permuted writes: all reads first
  int ci = colmap8(i);
  q[ci]      = f2tf32f(x1 * cs - x2 * sn);
  q[ci + 64] = f2tf32f(x2 * cs + x1 * sn);
}

// ---------------------------------------------------------------------------
// Split KV: exact K/V outputs; Kr (roped, tf32, interleaved), Vr (tf32, plain).
// ---------------------------------------------------------------------------
__global__ void split_rope_k_kernel(const float* __restrict__ KV,
                                    float* __restrict__ Kout,
                                    float* __restrict__ Vout,
                                    float* __restrict__ Kr,
                                    float* __restrict__ Vr) {
  const int tok = blockIdx.x;
  const int s = tok % NS;
  const int t = threadIdx.x;
  const float* kv = KV + (size_t)tok * 256;
  float vv = kv[128 + t];
  Kout[(size_t)tok * NDH + t] = kv[t];
  Vout[(size_t)tok * NDH + t] = vv;
  Vr[(size_t)tok * NDH + t] = f2tf32f(vv);
  if (t < 64) {
    float fr = 1.0f / powf(10000.0f, (float)(2 * t) / 128.0f);
    float ang = (float)s * fr;
    float sn, cs;
    sincosf(ang, &sn, &cs);
    float x1 = kv[t];
    float x2 = kv[t + 64];
    int ct = colmap8(t);
    Kr[(size_t)tok * NDH + ct]      = f2tf32f(x1 * cs - x2 * sn);
    Kr[(size_t)tok * NDH + ct + 64] = f2tf32f(x2 * cs + x1 * sn);
  }
}

// ===========================================================================
// Tensor-core flash attention, tf32 mma.sync, pipelined K/V double buffer.
// Q/K gmem layouts col-interleaved -> uint2 (LDS.64) fragment loads.
// Strides 136 words: LDS.64 bank64 = 4*gid+tg (conflict-free).
// ===========================================================================
#define AQ_STR 136
#define AVR_STR 136
#define QS_OFF 0
#define KS_OFF (128 * AQ_STR)                    // 17408
#define KS_SZ (64 * AQ_STR)                      // 8704
#define VR_OFF (KS_OFF + 2 * KS_SZ)              // 34816
#define VR_SZ (64 * AVR_STR)                     // 8704
#define ATTN_SMEM ((VR_OFF + 2 * VR_SZ) * 4)     // 208896 bytes

__global__ void __launch_bounds__(256, 1) attn_mma_kernel(
    const float* __restrict__ Q, const float* __restrict__ Kr,
    const float* __restrict__ Vr, float* __restrict__ O,
    const int* __restrict__ past) {
  extern __shared__ float sm[];
  uint32_t* smu = (uint32_t*)sm;
  const uint32_t sbase = smem_u32(sm);

  const int qt = (int)gridDim.x - 1 - (int)blockIdx.x;  // heavy tiles first
  const int h = blockIdx.y;
  const int b = blockIdx.z;
  const int tid = threadIdx.x;
  const int w = tid >> 5;
  const int lane = tid & 31;
  const int gid = lane >> 2;
  const int tg = lane & 3;
  const int q0 = qt * 128;
  const int pl = past[0];
  const float scale = 0.08838834764831845f;  // 1/sqrt(128)
  const int nkt = 2 * qt + 2;

  auto load_tile = [&](int kt) {
    const int s = kt & 1;
    const uint32_t ksb = sbase + (KS_OFF + s * KS_SZ) * 4;
    const uint32_t vrb = sbase + (VR_OFF + s * VR_SZ) * 4;
    const size_t tok0 = (size_t)(b * NS) + kt * 64;
#pragma unroll
    for (int i = 0; i < 8; i++) {
      int idx = tid + i * 256;
      int r = idx >> 5, c4 = idx & 31;
      cp_async16(ksb + (r * AQ_STR + c4 * 4) * 4, Kr + (tok0 + r) * NDH + c4 * 4);
    }
#pragma unroll
    for (int i = 0; i < 8; i++) {
      int idx = tid + i * 256;
      int r = idx >> 5, c4 = idx & 31;
      cp_async16(vrb + (r * AVR_STR + c4 * 4) * 4, Vr + (tok0 + r) * NDH + c4 * 4);
    }
    CP_ASYNC_COMMIT();
  };

  // Prologue: Q tile + tile 0 in one group.
#pragma unroll
  for (int i = 0; i < 16; i++) {
    int idx = tid + i * 256;
    int r = idx >> 5, c4 = idx & 31;
    cp_async16(sbase + (QS_OFF + r * AQ_STR + c4 * 4) * 4,
               Q + ((size_t)(b * NS + q0 + r)) * ND + h * NDH + c4 * 4);
  }
  load_tile(0);

  float oacc[16][4];
#pragma unroll
  for (int nf = 0; nf < 16; nf++)
#pragma unroll
    for (int r = 0; r < 4; r++) oacc[nf][r] = 0.f;
  float mrow0 = -1e30f, mrow1 = -1e30f;
  float lrow0 = 0.f, lrow1 = 0.f;

  const int r0 = w * 16 + gid;
  const int srcA = (lane & ~3) | (tg >> 1);
  const int srcB = (lane & ~3) | ((tg >> 1) + 2);

  for (int kt = 0; kt < nkt; kt++) {
    if (kt + 1 < nkt) {
      load_tile(kt + 1);
      cp_async_wait<1>();
    } else {
      cp_async_wait<0>();
    }
    __syncthreads();

    const uint32_t* ksb = smu + KS_OFF + (kt & 1) * KS_SZ;
    const uint32_t* vrb = smu + VR_OFF + (kt & 1) * VR_SZ;

    // ---- S = Q K^T (uint2 fragment loads; cols pre-interleaved) ----
    float sacc[8][4];
#pragma unroll
    for (int nf = 0; nf < 8; nf++)
#pragma unroll
      for (int r = 0; r < 4; r++) sacc[nf][r] = 0.f;

#pragma unroll
    for (int k8 = 0; k8 < 16; k8++) {
      uint32_t a[4];
      const uint32_t* ap = smu + QS_OFF + r0 * AQ_STR + k8 * 8 + 2 * tg;
      uint2 av0 = *(const uint2*)ap;
      uint2 av1 = *(const uint2*)(ap + 8 * AQ_STR);
      a[0] = av0.x;
      a[1] = av1.x;
      a[2] = av0.y;
      a[3] = av1.y;
#pragma unroll
      for (int nf = 0; nf < 8; nf++) {
        uint2 bv = *(const uint2*)(ksb + (nf * 8 + gid) * AQ_STR + k8 * 8 + 2 * tg);
        uint32_t bf[2] = {bv.x, bv.y};
        mma_tf32(sacc[nf], a, bf);
      }
    }

    // ---- scale + causal mask ----
    const bool partial = ((kt + 1) * 64 - 1) > (q0 + pl);
    if (partial) {
      const int L0 = q0 + pl + r0;
      const int L1 = L0 + 8;
      const int jb = kt * 64 + 2 * tg;
#pragma unroll
      for (int nf = 0; nf < 8; nf++) {
        int j0 = jb + nf * 8;
        sacc[nf][0] = (j0 <= L0) ? sacc[nf][0] * scale : -1e30f;
        sacc[nf][1] = (j0 + 1 <= L0) ? sacc[nf][1] * scale : -1e30f;
        sacc[nf][2] = (j0 <= L1) ? sacc[nf][2] * scale : -1e30f;
        sacc[nf][3] = (j0 + 1 <= L1) ? sacc[nf][3] * scale : -1e30f;
      }
    } else {
#pragma unroll
      for (int nf = 0; nf < 8; nf++)
#pragma unroll
        for (int r = 0; r < 4; r++) sacc[nf][r] *= scale;
    }

    // ---- online softmax ----
    float m0 = -1e30f, m1 = -1e30f;
#pragma unroll
    for (int nf = 0; nf < 8; nf++) {
      m0 = fmaxf(m0, fmaxf(sacc[nf][0], sacc[nf][1]));
      m1 = fmaxf(m1, fmaxf(sacc[nf][2], sacc[nf][3]));
    }
    m0 = fmaxf(m0, __shfl_xor_sync(0xffffffffu, m0, 1));
    m0 = fmaxf(m0, __shfl_xor_sync(0xffffffffu, m0, 2));
    m1 = fmaxf(m1, __shfl_xor_sync(0xffffffffu, m1, 1));
    m1 = fmaxf(m1, __shfl_xor_sync(0xffffffffu, m1, 2));

    const float mn0 = fmaxf(mrow0, m0);
    const float mn1 = fmaxf(mrow1, m1);
    const float al0 = __expf(mrow0 - mn0);
    const float al1 = __expf(mrow1 - mn1);
    mrow0 = mn0;
    mrow1 = mn1;

    uint32_t pc[8][4];
    float s0 = 0.f, s1 = 0.f;
#pragma unroll
    for (int nf = 0; nf < 8; nf++) {
      float p00 = __expf(sacc[nf][0] - mn0);
      float p01 = __expf(sacc[nf][1] - mn0);
      float p10 = __expf(sacc[nf][2] - mn1);
      float p11 = __expf(sacc[nf][3] - mn1);
      s0 += p00 + p01;
      s1 += p10 + p11;
      pc[nf][0] = f2tf32(p00);
      pc[nf][1] = f2tf32(p01);
      pc[nf][2] = f2tf32(p10);
      pc[nf][3] = f2tf32(p11);
    }
    s0 += __shfl_xor_sync(0xffffffffu, s0, 1);
    s0 += __shfl_xor_sync(0xffffffffu, s0, 2);
    s1 += __shfl_xor_sync(0xffffffffu, s1, 1);
    s1 += __shfl_xor_sync(0xffffffffu, s1, 2);
    lrow0 = lrow0 * al0 + s0;
    lrow1 = lrow1 * al1 + s1;

#pragma unroll
    for (int nf = 0; nf < 16; nf++) {
      oacc[nf][0] *= al0;
      oacc[nf][1] *= al0;
      oacc[nf][2] *= al1;
      oacc[nf][3] *= al1;
    }

    // ---- O += P V : P C-layout -> A-layout via intra-quad shuffles ----
#pragma unroll
    for (int k8 = 0; k8 < 8; k8++) {
      uint32_t t00 = __shfl_sync(0xffffffffu, pc[k8][0], srcA);
      uint32_t t01 = __shfl_sync(0xffffffffu, pc[k8][1], srcA);
      uint32_t t10 = __shfl_sync(0xffffffffu, pc[k8][2], srcA);
      uint32_t t11 = __shfl_sync(0xffffffffu, pc[k8][3], srcA);
      uint32_t u00 = __shfl_sync(0xffffffffu, pc[k8][0], srcB);
      uint32_t u01 = __shfl_sync(0xffffffffu, pc[k8][1], srcB);
      uint32_t u10 = __shfl_sync(0xffffffffu, pc[k8][2], srcB);
      uint32_t u11 = __shfl_sync(0xffffffffu, pc[k8][3], srcB);
      uint32_t a[4];
      a[0] = (tg & 1) ? t01 : t00;
      a[1] = (tg & 1) ? t11 : t10;
      a[2] = (tg & 1) ? u01 : u00;
      a[3] = (tg & 1) ? u11 : u10;
#pragma unroll
      for (int nf = 0; nf < 16; nf++) {
        uint32_t bf[2];
        const uint32_t* bp = vrb + (k8 * 8 + tg) * AVR_STR + nf * 8 + gid;
        bf[0] = bp[0];
        bf[1] = bp[4 * AVR_STR];
        mma_tf32(oacc[nf], a, bf);
      }
    }
    __syncthreads();
  }

  // ---- epilogue: normalize, tf32-round, write O col-interleaved ----
  const float inv0 = 1.0f / lrow0;
  const float inv1 = 1.0f / lrow1;
  const size_t grow0 = (size_t)(b * NS + q0 + r0) * ND + h * NDH;
  const size_t grow1 = grow0 + (size_t)8 * ND;
#pragma unroll
  for (int nf = 0; nf < 16; nf++) {
    int c0 = nf * 8 + 2 * tg;
    int m0c = colmap8(c0), m1c = colmap8(c0 + 1);
    O[grow0 + m0c] = f2tf32f(oacc[nf][0] * inv0);
    O[grow0 + m1c] = f2tf32f(oacc[nf][1] * inv0);
    O[grow1 + m0c] = f2tf32f(oacc[nf][2] * inv1);
    O[grow1 + m1c] = f2tf32f(oacc[nf][3] * inv1);
  }
}

// ---------------------------------------------------------------------------
extern "C" void kernel_launch(void* const* d_in, const int* in_sizes, int n_in,
                              void* d_out, int out_size) {
  const float* x   = (const float*)d_in[0];
  const float* wq  = (const float*)d_in[1];
  const float* wkv = (const float*)d_in[2];
  const float* wo  = (const float*)d_in[3];
  const int*  past = (const int*)d_in[4];

  float* out  = (float*)d_out;
  float* Kout = out + (size_t)NTOK * ND;
  float* Vout = Kout + (size_t)NTOK * NDH;

  float *Qs, *Os, *KVs, *Krs, *Vrs, *xr, *wqr, *wor, *wkvT;
  cudaGetSymbolAddress((void**)&Qs, g_Q);
  cudaGetSymbolAddress((void**)&Os, g_O);
  cudaGetSymbolAddress((void**)&KVs, g_KV);
  cudaGetSymbolAddress((void**)&Krs, g_Kr);
  cudaGetSymbolAddress((void**)&Vrs, g_Vr);
  cudaGetSymbolAddress((void**)&xr, g_xr);
  cudaGetSymbolAddress((void**)&wqr, g_wqr);
  cudaGetSymbolAddress((void**)&wor, g_wor);
  cudaGetSymbolAddress((void**)&wkvT, g_wkvT);

  cudaFuncSetAttribute(tf32_mma_gemm,
                       cudaFuncAttributeMaxDynamicSharedMemorySize, MMA_SMEM);
  cudaFuncSetAttribute(attn_mma_kernel,
                       cudaFuncAttributeMaxDynamicSharedMemorySize, ATTN_SMEM);

  // Pre-round operands to tf32 in gmem (wo also col-interleaved)
  round_tf32_kernel<<<(NTOK * ND / 4 + 255) / 256, 256>>>(x, xr, NTOK * ND / 4);
  round_tf32_kernel<<<(ND * ND / 4 + 255) / 256, 256>>>(wq, wqr, ND * ND / 4);
  round_tf32_ilv_kernel<<<(ND * ND / 4 + 255) / 256, 256>>>(wo, wor, ND * ND / 4);
  transpose_round_kernel<<<dim3(ND / 32, 256 / 32), dim3(32, 8)>>>(wkv, wkvT);

  // Q = x @ wq.T
  tf32_mma_gemm<<<dim3(ND / TBN, NTOK / TBM), 256, MMA_SMEM>>>(
      xr, wqr, Qs, NTOK, ND, ND);
  // KV = x @ wkv
  tf32_mma_gemm<<<dim3(256 / TBN, NTOK / TBM), 256, MMA_SMEM>>>(
      xr, wkvT, KVs, NTOK, 256, ND);
  // RoPE Q in place (tf32 + interleave)
  rope_q_kernel<<<NTOK, 1024>>>(Qs, past);
  // Split K/V, make attention-side scratch
  split_rope_k_kernel<<<NTOK, 128>>>(KVs, Kout, Vout, Krs, Vrs);
  // Flash attention (tf32 tensor cores, pipelined, LDS.64 fragments)
  attn_mma_kernel<<<dim3(NS / 128, NH, NB), 256, ATTN_SMEM>>>(
      Qs, Krs, Vrs, Os, past);
  // out = O @ wo.T (both sides col-interleaved in K)
  tf32_mma_gemm<<<dim3(ND / TBN, NTOK / TBM), 256, MMA_SMEM>>>(
      Os, wor, out, NTOK, ND, ND);
}

// round 8
// speedup vs baseline: 3.6939x; 1.0213x over previous
#include <cuda_runtime.h>
#include <cstdint>

#define NB   2
#define NS   2048
#define ND   2048
#define NH   16
#define NDH  128
#define NTOK (NB * NS)

// Scratch (device globals: no allocation allowed in kernel_launch)
__device__ float g_Q  [(size_t)NTOK * ND];      // roped Q (tf32, col-interleaved)
__device__ float g_O  [(size_t)NTOK * ND];      // attention out (tf32, col-interleaved)
__device__ float g_KV [(size_t)NTOK * 2 * NDH]; // KV projection result
__device__ float g_Kr [(size_t)NTOK * NDH];     // roped K (tf32, col-interleaved)
__device__ float g_Vt [(size_t)NDH * NTOK];     // V^T (tf32), key dim pair-interleaved
__device__ float g_xr [(size_t)NTOK * ND];      // x  (tf32, plain)
__device__ float g_wqr[(size_t)ND * ND];        // wq (tf32, plain)
__device__ float g_wor[(size_t)ND * ND];        // wo (tf32, col-interleaved)
__device__ float g_wkvT[(size_t)256 * ND];      // wkv^T (tf32, plain)

// ===========================================================================
// Helpers
// ===========================================================================
__device__ __forceinline__ uint32_t smem_u32(const void* p) {
  uint32_t a;
  asm("{ .reg .u64 t; cvta.to.shared.u64 t, %1; cvt.u32.u64 %0, t; }"
      : "=r"(a) : "l"(p));
  return a;
}
__device__ __forceinline__ void cp_async16(uint32_t dst, const void* src) {
  asm volatile("cp.async.cg.shared.global [%0], [%1], 16;" ::"r"(dst), "l"(src));
}
#define CP_ASYNC_COMMIT() asm volatile("cp.async.commit_group;" ::: "memory")
template <int N>
__device__ __forceinline__ void cp_async_wait() {
  asm volatile("cp.async.wait_group %0;" ::"n"(N) : "memory");
}
__device__ __forceinline__ uint32_t f2tf32(float x) {
  uint32_t r;
  asm("cvt.rna.tf32.f32 %0, %1;" : "=r"(r) : "f"(x));
  return r;
}
__device__ __forceinline__ float f2tf32f(float x) {
  return __uint_as_float(f2tf32(x));
}
__device__ __forceinline__ void mma_tf32(float* c, const uint32_t* a,
                                         const uint32_t* b) {
  asm volatile(
      "mma.sync.aligned.m16n8k8.row.col.f32.tf32.tf32.f32 "
      "{%0,%1,%2,%3}, {%4,%5,%6,%7}, {%8,%9}, {%0,%1,%2,%3};"
      : "+f"(c[0]), "+f"(c[1]), "+f"(c[2]), "+f"(c[3])
      : "r"(a[0]), "r"(a[1]), "r"(a[2]), "r"(a[3]), "r"(b[0]), "r"(b[1]));
}
// Pair interleave within each 8-group: fragment pair (c, c+4) -> adjacent.
__device__ __forceinline__ int colmap8(int c) {
  int r = c & 7;
  return (c & ~7) | ((r < 4) ? (r << 1) : (((r - 4) << 1) | 1));
}
// Inverse: word slot w -> original index.
__device__ __forceinline__ int invmap8(int w) {
  int r = w & 7;
  return (w & ~7) | ((r & 1) ? ((r >> 1) + 4) : (r >> 1));
}

// ===========================================================================
// tf32 mma.sync GEMM: C[M,N] = A[M,K] @ B[N,K]^T. Operands PRE-ROUNDED tf32.
// Tile 128x128x32, 256 threads, 3 stages, single barrier per chunk.
// ===========================================================================
#define TBM 128
#define TBN 128
#define TBK 32
#define TSTRIDE 36
#define TILE_FLOATS (TBM * TSTRIDE)
#define STAGE_FLOATS (2 * TILE_FLOATS)
#define TSTAGES 3
#define MMA_SMEM (TSTAGES * STAGE_FLOATS * 4)

__global__ void __launch_bounds__(256, 2)
tf32_mma_gemm(const float* __restrict__ A, const float* __restrict__ B,
              float* __restrict__ C, int M, int N, int K) {
  extern __shared__ float sm[];
  const uint32_t* smu = (const uint32_t*)sm;
  const int tid = threadIdx.x;
  const int wid = tid >> 5;
  const int lane = tid & 31;
  const int gid = lane >> 2;
  const int tg = lane & 3;
  const int wm = wid & 1;
  const int wn = wid >> 1;
  const int bm = blockIdx.y * TBM;
  const int bn = blockIdx.x * TBN;
  const int nchunks = K / TBK;

  const float* gA = A + (size_t)bm * K;
  const float* gB = B + (size_t)bn * K;
  const uint32_t sbase = smem_u32(sm);

  auto load_chunk = [&](int c) {
    const int s = c % TSTAGES;
    const uint32_t sa = sbase + s * STAGE_FLOATS * 4;
    const uint32_t sbb = sa + TILE_FLOATS * 4;
    const int k0 = c * TBK;
#pragma unroll
    for (int i = 0; i < 4; i++) {
      int idx = tid + i * 256;
      int r = idx >> 3, c4 = idx & 7;
      cp_async16(sa + (r * TSTRIDE + c4 * 4) * 4, gA + (size_t)r * K + k0 + c4 * 4);
    }
#pragma unroll
    for (int i = 0; i < 4; i++) {
      int idx = tid + i * 256;
      int r = idx >> 3, c4 = idx & 7;
      cp_async16(sbb + (r * TSTRIDE + c4 * 4) * 4, gB + (size_t)r * K + k0 + c4 * 4);
    }
    CP_ASYNC_COMMIT();
  };

  float acc[4][4][4];
#pragma unroll
  for (int mf = 0; mf < 4; mf++)
#pragma unroll
    for (int nf = 0; nf < 4; nf++)
#pragma unroll
      for (int r = 0; r < 4; r++) acc[mf][nf][r] = 0.f;

  load_chunk(0);
  load_chunk(1);

  for (int i = 0; i < nchunks; i++) {
    if (i < nchunks - 1)
      cp_async_wait<1>();
    else
      cp_async_wait<0>();
    __syncthreads();
    // Single barrier per chunk: stage (i+2)%3's previous readers (iter i-1)
    // are guaranteed past by the sync above.
    if (i + 2 < nchunks) load_chunk(i + 2);

    const uint32_t* As = smu + (i % TSTAGES) * STAGE_FLOATS;
    const uint32_t* Bs = As + TILE_FLOATS;

#pragma unroll
    for (int k8 = 0; k8 < 4; k8++) {
      uint32_t a[4][4], b[4][2];
#pragma unroll
      for (int mf = 0; mf < 4; mf++) {
        const uint32_t* ap = As + (wm * 64 + mf * 16 + gid) * TSTRIDE + k8 * 8 + tg;
        a[mf][0] = ap[0];
        a[mf][1] = ap[8 * TSTRIDE];
        a[mf][2] = ap[4];
        a[mf][3] = ap[8 * TSTRIDE + 4];
      }
#pragma unroll
      for (int nf = 0; nf < 4; nf++) {
        const uint32_t* bp = Bs + (wn * 32 + nf * 8 + gid) * TSTRIDE + k8 * 8 + tg;
        b[nf][0] = bp[0];
        b[nf][1] = bp[4];
      }
#pragma unroll
      for (int mf = 0; mf < 4; mf++)
#pragma unroll
        for (int nf = 0; nf < 4; nf++) mma_tf32(acc[mf][nf], a[mf], b[nf]);
    }
  }

#pragma unroll
  for (int mf = 0; mf < 4; mf++) {
    int row0 = bm + wm * 64 + mf * 16 + gid;
#pragma unroll
    for (int nf = 0; nf < 4; nf++) {
      int col = bn + wn * 32 + nf * 8 + 2 * tg;
      *(float2*)(C + (size_t)row0 * N + col) =
          make_float2(acc[mf][nf][0], acc[mf][nf][1]);
      *(float2*)(C + (size_t)(row0 + 8) * N + col) =
          make_float2(acc[mf][nf][2], acc[mf][nf][3]);
    }
  }
}

// ---------------------------------------------------------------------------
// Elementwise tf32 rounding; interleaved variant for wo.
// ---------------------------------------------------------------------------
__global__ void round_tf32_kernel(const float* __restrict__ in,
                                  float* __restrict__ out, int n4) {
  int i = blockIdx.x * 256 + threadIdx.x;
  if (i < n4) {
    float4 v = ((const float4*)in)[i];
    v.x = f2tf32f(v.x);
    v.y = f2tf32f(v.y);
    v.z = f2tf32f(v.z);
    v.w = f2tf32f(v.w);
    ((float4*)out)[i] = v;
  }
}

__global__ void round_tf32_ilv_kernel(const float* __restrict__ in,
                                      float* __restrict__ out, int n4) {
  int i = blockIdx.x * 256 + threadIdx.x;
  if (i < n4) {
    float4 v = ((const float4*)in)[i];
    int c = i * 4;
    out[colmap8(c + 0)] = f2tf32f(v.x);
    out[colmap8(c + 1)] = f2tf32f(v.y);
    out[colmap8(c + 2)] = f2tf32f(v.z);
    out[colmap8(c + 3)] = f2tf32f(v.w);
  }
}

// ---------------------------------------------------------------------------
// Transpose + round: wkv [2048][256] -> wkvT [256][2048] (tf32).
// ---------------------------------------------------------------------------
__global__ void transpose_round_kernel(const float* __restrict__ in,
                                       float* __restrict__ out) {
  __shared__ float t[32][33];
  const int k0 = blockIdx.x * 32;
  const int n0 = blockIdx.y * 32;
  const int tx = threadIdx.x;
  const int ty = threadIdx.y;
#pragma unroll
  for (int j = 0; j < 4; j++)
    t[ty + 8 * j][tx] = in[(size_t)(k0 + ty + 8 * j) * 256 + n0 + tx];
  __syncthreads();
#pragma unroll
  for (int j = 0; j < 4; j++)
    out[(size_t)(n0 + ty + 8 * j) * 2048 + k0 + tx] = f2tf32f(t[tx][ty + 8 * j]);
}

// ---------------------------------------------------------------------------
// V transpose: g_KV[tok][128+d] -> g_Vt[d][keyslot], keys pair-interleaved
// within 8-groups (key s stored at word colmap8(s)), tf32-rounded.
// ---------------------------------------------------------------------------
__global__ void transpose_v_kernel(const float* __restrict__ KV,
                                   float* __restrict__ Vt) {
  __shared__ float t[32][33];
  const int tok0 = blockIdx.x * 32;
  const int d0 = blockIdx.y * 32;
  const int tx = threadIdx.x;
  const int ty = threadIdx.y;
#pragma unroll
  for (int j = 0; j < 4; j++)
    t[ty + 8 * j][tx] = KV[(size_t)(tok0 + ty + 8 * j) * 256 + 128 + d0 + tx];
  __syncthreads();
#pragma unroll
  for (int j = 0; j < 4; j++) {
    int s = invmap8(tx);  // word slot tx holds key invmap8(tx)
    Vt[(size_t)(d0 + ty + 8 * j) * NTOK + tok0 + tx] = f2tf32f(t[s][ty + 8 * j]);
  }
}

// ---------------------------------------------------------------------------
// RoPE on Q, in-place, tf32-rounded + col-interleaved (per head).
// ---------------------------------------------------------------------------
__global__ void rope_q_kernel(float* __restrict__ Q, const int* __restrict__ past) {
  const int tok = blockIdx.x;
  const int s = tok % NS;
  const int pos = past[0] + s;
  const int t = threadIdx.x;
  const int h = t >> 6;
  const int i = t & 63;
  float fr = 1.0f / powf(10000.0f, (float)(2 * i) / 128.0f);
  float ang = (float)pos * fr;
  float sn, cs;
  sincosf(ang, &sn, &cs);
  float* q = Q + (size_t)tok * ND + h * NDH;
  float x1 = q[i];
  float x2 = q[i + 64];
  __syncthreads();  // in-place permuted writes: all reads first
  int ci = colmap8(i);
  q[ci]      = f2tf32f(x1 * cs - x2 * sn);
  q[ci + 64] = f2tf32f(x2 * cs + x1 * sn);
}

// ---------------------------------------------------------------------------
// Split KV: exact K/V outputs; Kr (roped, tf32, interleaved).
// ---------------------------------------------------------------------------
__global__ void split_rope_k_kernel(const float* __restrict__ KV,
                                    float* __restrict__ Kout,
                                    float* __restrict__ Vout,
                                    float* __restrict__ Kr) {
  const int tok = blockIdx.x;
  const int s = tok % NS;
  const int t = threadIdx.x;
  const float* kv = KV + (size_t)tok * 256;
  Kout[(size_t)tok * NDH + t] = kv[t];
  Vout[(size_t)tok * NDH + t] = kv[128 + t];
  if (t < 64) {
    float fr = 1.0f / powf(10000.0f, (float)(2 * t) / 128.0f);
    float ang = (float)s * fr;
    float sn, cs;
    sincosf(ang, &sn, &cs);
    float x1 = kv[t];
    float x2 = kv[t + 64];
    int ct = colmap8(t);
    Kr[(size_t)tok * NDH + ct]      = f2tf32f(x1 * cs - x2 * sn);
    Kr[(size_t)tok * NDH + ct + 64] = f2tf32f(x2 * cs + x1 * sn);
  }
}

// ===========================================================================
// Tensor-core flash attention, tf32 mma.sync, pipelined K/V double buffer.
// Q/K col-interleaved and V^T key-interleaved -> all fragment loads LDS.64.
// Smem (words): qs[128][136] | ks[2][64][136] | vt[2][128][72]
// ===========================================================================
#define AQ_STR 136
#define AVT_STR 72
#define QS_OFF 0
#define KS_OFF (128 * AQ_STR)                    // 17408
#define KS_SZ (64 * AQ_STR)                      // 8704
#define VT_OFF (KS_OFF + 2 * KS_SZ)              // 34816
#define VT_SZ (128 * AVT_STR)                    // 9216
#define ATTN_SMEM ((VT_OFF + 2 * VT_SZ) * 4)     // 212992 bytes

__global__ void __launch_bounds__(256, 1) attn_mma_kernel(
    const float* __restrict__ Q, const float* __restrict__ Kr,
    const float* __restrict__ Vt, float* __restrict__ O,
    const int* __restrict__ past) {
  extern __shared__ float sm[];
  uint32_t* smu = (uint32_t*)sm;
  const uint32_t sbase = smem_u32(sm);

  const int qt = (int)gridDim.x - 1 - (int)blockIdx.x;  // heavy tiles first
  const int h = blockIdx.y;
  const int b = blockIdx.z;
  const int tid = threadIdx.x;
  const int w = tid >> 5;
  const int lane = tid & 31;
  const int gid = lane >> 2;
  const int tg = lane & 3;
  const int q0 = qt * 128;
  const int pl = past[0];
  const float scale = 0.08838834764831845f;  // 1/sqrt(128)
  const int nkt = 2 * qt + 2;

  auto load_tile = [&](int kt) {
    const int s = kt & 1;
    const uint32_t ksb = sbase + (KS_OFF + s * KS_SZ) * 4;
    const uint32_t vtb = sbase + (VT_OFF + s * VT_SZ) * 4;
    const size_t tok0 = (size_t)(b * NS) + kt * 64;
#pragma unroll
    for (int i = 0; i < 8; i++) {
      int idx = tid + i * 256;
      int r = idx >> 5, c4 = idx & 31;
      cp_async16(ksb + (r * AQ_STR + c4 * 4) * 4, Kr + (tok0 + r) * NDH + c4 * 4);
    }
    // V^T tile: 128 dh-rows x 64 keys (key slots pre-interleaved in gmem)
#pragma unroll
    for (int i = 0; i < 8; i++) {
      int idx = tid + i * 256;
      int r = idx >> 4, c4 = idx & 15;  // dh row r, 16B chunk c4
      cp_async16(vtb + (r * AVT_STR + c4 * 4) * 4,
                 Vt + (size_t)r * NTOK + tok0 + c4 * 4);
    }
    CP_ASYNC_COMMIT();
  };

  // Prologue: Q tile + tile 0 in one group.
#pragma unroll
  for (int i = 0; i < 16; i++) {
    int idx = tid + i * 256;
    int r = idx >> 5, c4 = idx & 31;
    cp_async16(sbase + (QS_OFF + r * AQ_STR + c4 * 4) * 4,
               Q + ((size_t)(b * NS + q0 + r)) * ND + h * NDH + c4 * 4);
  }
  load_tile(0);

  float oacc[16][4];
#pragma unroll
  for (int nf = 0; nf < 16; nf++)
#pragma unroll
    for (int r = 0; r < 4; r++) oacc[nf][r] = 0.f;
  float mrow0 = -1e30f, mrow1 = -1e30f;
  float lrow0 = 0.f, lrow1 = 0.f;

  const int r0 = w * 16 + gid;
  const int srcA = (lane & ~3) | (tg >> 1);
  const int srcB = (lane & ~3) | ((tg >> 1) + 2);

  for (int kt = 0; kt < nkt; kt++) {
    if (kt + 1 < nkt) {
      load_tile(kt + 1);
      cp_async_wait<1>();
    } else {
      cp_async_wait<0>();
    }
    __syncthreads();

    const uint32_t* ksb = smu + KS_OFF + (kt & 1) * KS_SZ;
    const uint32_t* vtb = smu + VT_OFF + (kt & 1) * VT_SZ;

    // ---- S = Q K^T (LDS.64 fragments; cols pre-interleaved) ----
    float sacc[8][4];
#pragma unroll
    for (int nf = 0; nf < 8; nf++)
#pragma unroll
      for (int r = 0; r < 4; r++) sacc[nf][r] = 0.f;

#pragma unroll
    for (int k8 = 0; k8 < 16; k8++) {
      uint32_t a[4];
      const uint32_t* ap = smu + QS_OFF + r0 * AQ_STR + k8 * 8 + 2 * tg;
      uint2 av0 = *(const uint2*)ap;
      uint2 av1 = *(const uint2*)(ap + 8 * AQ_STR);
      a[0] = av0.x;
      a[1] = av1.x;
      a[2] = av0.y;
      a[3] = av1.y;
#pragma unroll
      for (int nf = 0; nf < 8; nf++) {
        uint2 bv = *(const uint2*)(ksb + (nf * 8 + gid) * AQ_STR + k8 * 8 + 2 * tg);
        uint32_t bf[2] = {bv.x, bv.y};
        mma_tf32(sacc[nf], a, bf);
      }
    }

    // ---- scale + causal mask ----
    const bool partial = ((kt + 1) * 64 - 1) > (q0 + pl);
    if (partial) {
      const int L0 = q0 + pl + r0;
      const int L1 = L0 + 8;
      const int jb = kt * 64 + 2 * tg;
#pragma unroll
      for (int nf = 0; nf < 8; nf++) {
        int j0 = jb + nf * 8;
        sacc[nf][0] = (j0 <= L0) ? sacc[nf][0] * scale : -1e30f;
        sacc[nf][1] = (j0 + 1 <= L0) ? sacc[nf][1] * scale : -1e30f;
        sacc[nf][2] = (j0 <= L1) ? sacc[nf][2] * scale : -1e30f;
        sacc[nf][3] = (j0 + 1 <= L1) ? sacc[nf][3] * scale : -1e30f;
      }
    } else {
#pragma unroll
      for (int nf = 0; nf < 8; nf++)
#pragma unroll
        for (int r = 0; r < 4; r++) sacc[nf][r] *= scale;
    }

    // ---- online softmax ----
    float m0 = -1e30f, m1 = -1e30f;
#pragma unroll
    for (int nf = 0; nf < 8; nf++) {
      m0 = fmaxf(m0, fmaxf(sacc[nf][0], sacc[nf][1]));
      m1 = fmaxf(m1, fmaxf(sacc[nf][2], sacc[nf][3]));
    }
    m0 = fmaxf(m0, __shfl_xor_sync(0xffffffffu, m0, 1));
    m0 = fmaxf(m0, __shfl_xor_sync(0xffffffffu, m0, 2));
    m1 = fmaxf(m1, __shfl_xor_sync(0xffffffffu, m1, 1));
    m1 = fmaxf(m1, __shfl_xor_sync(0xffffffffu, m1, 2));

    const float mn0 = fmaxf(mrow0, m0);
    const float mn1 = fmaxf(mrow1, m1);
    const float al0 = __expf(mrow0 - mn0);
    const float al1 = __expf(mrow1 - mn1);
    mrow0 = mn0;
    mrow1 = mn1;

    uint32_t pc[8][4];
    float s0 = 0.f, s1 = 0.f;
#pragma unroll
    for (int nf = 0; nf < 8; nf++) {
      float p00 = __expf(sacc[nf][0] - mn0);
      float p01 = __expf(sacc[nf][1] - mn0);
      float p10 = __expf(sacc[nf][2] - mn1);
      float p11 = __expf(sacc[nf][3] - mn1);
      s0 += p00 + p01;
      s1 += p10 + p11;
      pc[nf][0] = f2tf32(p00);
      pc[nf][1] = f2tf32(p01);
      pc[nf][2] = f2tf32(p10);
      pc[nf][3] = f2tf32(p11);
    }
    s0 += __shfl_xor_sync(0xffffffffu, s0, 1);
    s0 += __shfl_xor_sync(0xffffffffu, s0, 2);
    s1 += __shfl_xor_sync(0xffffffffu, s1, 1);
    s1 += __shfl_xor_sync(0xffffffffu, s1, 2);
    lrow0 = lrow0 * al0 + s0;
    lrow1 = lrow1 * al1 + s1;

#pragma unroll
    for (int nf = 0; nf < 16; nf++) {
      oacc[nf][0] *= al0;
      oacc[nf][1] *= al0;
      oacc[nf][2] *= al1;
      oacc[nf][3] *= al1;
    }

    // ---- O += P V : P via intra-quad shuffles; V^T fragments via LDS.64 ----
#pragma unroll
    for (int k8 = 0; k8 < 8; k8++) {
      uint32_t t00 = __shfl_sync(0xffffffffu, pc[k8][0], srcA);
      uint32_t t01 = __shfl_sync(0xffffffffu, pc[k8][1], srcA);
      uint32_t t10 = __shfl_sync(0xffffffffu, pc[k8][2], srcA);
      uint32_t t11 = __shfl_sync(0xffffffffu, pc[k8][3], srcA);
      uint32_t u00 = __shfl_sync(0xffffffffu, pc[k8][0], srcB);
      uint32_t u01 = __shfl_sync(0xffffffffu, pc[k8][1], srcB);
      uint32_t u10 = __shfl_sync(0xffffffffu, pc[k8][2], srcB);
      uint32_t u11 = __shfl_sync(0xffffffffu, pc[k8][3], srcB);
      uint32_t a[4];
      a[0] = (tg & 1) ? t01 : t00;
      a[1] = (tg & 1) ? t11 : t10;
      a[2] = (tg & 1) ? u01 : u00;
      a[3] = (tg & 1) ? u11 : u10;
#pragma unroll
      for (int nf = 0; nf < 16; nf++) {
        uint2 bv = *(const uint2*)(vtb + (nf * 8 + gid) * AVT_STR + k8 * 8 + 2 * tg);
        uint32_t bf[2] = {bv.x, bv.y};
        mma_tf32(oacc[nf], a, bf);
      }
    }
    __syncthreads();
  }

  // ---- epilogue: normalize, tf32-round, write O col-interleaved ----
  const float inv0 = 1.0f / lrow0;
  const float inv1 = 1.0f / lrow1;
  const size_t grow0 = (size_t)(b * NS + q0 + r0) * ND + h * NDH;
  const size_t grow1 = grow0 + (size_t)8 * ND;
#pragma unroll
  for (int nf = 0; nf < 16; nf++) {
    int c0 = nf * 8 + 2 * tg;
    int m0c = colmap8(c0), m1c = colmap8(c0 + 1);
    O[grow0 + m0c] = f2tf32f(oacc[nf][0] * inv0);
    O[grow0 + m1c] = f2tf32f(oacc[nf][1] * inv0);
    O[grow1 + m0c] = f2tf32f(oacc[nf][2] * inv1);
    O[grow1 + m1c] = f2tf32f(oacc[nf][3] * inv1);
  }
}

// ---------------------------------------------------------------------------
extern "C" void kernel_launch(void* const* d_in, const int* in_sizes, int n_in,
                              void* d_out, int out_size) {
  const float* x   = (const float*)d_in[0];
  const float* wq  = (const float*)d_in[1];
  const float* wkv = (const float*)d_in[2];
  const float* wo  = (const float*)d_in[3];
  const int*  past = (const int*)d_in[4];

  float* out  = (float*)d_out;
  float* Kout = out + (size_t)NTOK * ND;
  float* Vout = Kout + (size_t)NTOK * NDH;

  float *Qs, *Os, *KVs, *Krs, *Vts, *xr, *wqr, *wor, *wkvT;
  cudaGetSymbolAddress((void**)&Qs, g_Q);
  cudaGetSymbolAddress((void**)&Os, g_O);
  cudaGetSymbolAddress((void**)&KVs, g_KV);
  cudaGetSymbolAddress((void**)&Krs, g_Kr);
  cudaGetSymbolAddress((void**)&Vts, g_Vt);
  cudaGetSymbolAddress((void**)&xr, g_xr);
  cudaGetSymbolAddress((void**)&wqr, g_wqr);
  cudaGetSymbolAddress((void**)&wor, g_wor);
  cudaGetSymbolAddress((void**)&wkvT, g_wkvT);

  cudaFuncSetAttribute(tf32_mma_gemm,
                       cudaFuncAttributeMaxDynamicSharedMemorySize, MMA_SMEM);
  cudaFuncSetAttribute(attn_mma_kernel,
                       cudaFuncAttributeMaxDynamicSharedMemorySize, ATTN_SMEM);

  // Pre-round operands to tf32 in gmem (wo also col-interleaved)
  round_tf32_kernel<<<(NTOK * ND / 4 + 255) / 256, 256>>>(x, xr, NTOK * ND / 4);
  round_tf32_kernel<<<(ND * ND / 4 + 255) / 256, 256>>>(wq, wqr, ND * ND / 4);
  round_tf32_ilv_kernel<<<(ND * ND / 4 + 255) / 256, 256>>>(wo, wor, ND * ND / 4);
  transpose_round_kernel<<<dim3(ND / 32, 256 / 32), dim3(32, 8)>>>(wkv, wkvT);

  // Q = x @ wq.T
  tf32_mma_gemm<<<dim3(ND / TBN, NTOK / TBM), 256, MMA_SMEM>>>(
      xr, wqr, Qs, NTOK, ND, ND);
  // KV = x @ wkv
  tf32_mma_gemm<<<dim3(256 / TBN, NTOK / TBM), 256, MMA_SMEM>>>(
      xr, wkvT, KVs, NTOK, 256, ND);
  // RoPE Q in place (tf32 + interleave)
  rope_q_kernel<<<NTOK, 1024>>>(Qs, past);
  // Split K/V to outputs; roped K scratch
  split_rope_k_kernel<<<NTOK, 128>>>(KVs, Kout, Vout, Krs);
  // V^T with interleaved key slots (for LDS.64 PV fragments)
  transpose_v_kernel<<<dim3(NTOK / 32, NDH / 32), dim3(32, 8)>>>(KVs, Vts);
  // Flash attention (tf32 tensor cores, pipelined, all-LDS.64 fragments)
  attn_mma_kernel<<<dim3(NS / 128, NH, NB), 256, ATTN_SMEM>>>(
      Qs, Krs, Vts, Os, past);
  // out = O @ wo.T (both sides col-interleaved in K)
  tf32_mma_gemm<<<dim3(ND / TBN, NTOK / TBM), 256, MMA_SMEM>>>(
      Os, wor, out, NTOK, ND, ND);
}